// round 1
// baseline (speedup 1.0000x reference)
#include <cuda_runtime.h>
#include <cuda_bf16.h>
#include <cstdint>

// Problem constants
#define B_   4
#define N_   1024
#define DIM_ 512
#define H_   8
#define D_   64
#define BH_  32          // B_*H_
#define SCALE_ 0.125f    // 64^-0.5

// ---------------------------------------------------------------------------
// Scratch (static __device__ arrays: allocation-free, harness-legal)
// ---------------------------------------------------------------------------
__device__ float g_q[BH_ * N_ * D_];           // [bh][i][d], pre-scaled
__device__ float g_k[BH_ * N_ * D_];           // [bh][j][d]
__device__ float g_v[BH_ * N_ * D_];           // [bh][j][d]
__device__ float g_attn[(size_t)BH_ * N_ * N_];// [bh][i][j] sim -> attn in place
__device__ float g_o[B_ * N_ * (H_ * D_)];     // [token][h*64+d]

// ---------------------------------------------------------------------------
// Kernel 1: qkv = x @ w_qkv, scattered into head-major Q/K/V (+scale on Q)
//   M=4096, K=512, N=1536.  Tile 64x64, BK=16, 256 thr, 4x4 microtile.
// ---------------------------------------------------------------------------
__global__ void __launch_bounds__(256) qkv_gemm(const float* __restrict__ X,
                                               const float* __restrict__ W) {
    __shared__ __align__(16) float As[16][68];  // As[k][m] (padded)
    __shared__ __align__(16) float Bs[16][64];  // Bs[k][n]
    const int tid = threadIdx.x;
    const int tx = tid & 15, ty = tid >> 4;
    const int row0 = blockIdx.y * 64;
    const int col0 = blockIdx.x * 64;
    const int ar = tid >> 2, ak = (tid & 3) << 2;   // A-tile load coords
    const int br = tid >> 4, bc = (tid & 15) << 2;  // B-tile load coords

    float acc[4][4] = {};
    for (int k0 = 0; k0 < DIM_; k0 += 16) {
        float4 a = *(const float4*)(X + (size_t)(row0 + ar) * DIM_ + k0 + ak);
        As[ak + 0][ar] = a.x; As[ak + 1][ar] = a.y;
        As[ak + 2][ar] = a.z; As[ak + 3][ar] = a.w;
        *(float4*)(&Bs[br][bc]) =
            *(const float4*)(W + (size_t)(k0 + br) * 1536 + col0 + bc);
        __syncthreads();
#pragma unroll
        for (int kk = 0; kk < 16; kk++) {
            float4 a4 = *(float4*)(&As[kk][ty << 2]);
            float4 b4 = *(float4*)(&Bs[kk][tx << 2]);
            float av[4] = {a4.x, a4.y, a4.z, a4.w};
            float bv[4] = {b4.x, b4.y, b4.z, b4.w};
#pragma unroll
            for (int i = 0; i < 4; i++)
#pragma unroll
                for (int j = 0; j < 4; j++)
                    acc[i][j] = fmaf(av[i], bv[j], acc[i][j]);
        }
        __syncthreads();
    }
    // epilogue: col0 aligned to 64 -> whole tile is one (part, head)
    const int part = col0 >> 9;            // 0=q 1=k 2=v
    const int h    = (col0 >> 6) & 7;
    float* dst = (part == 0) ? g_q : (part == 1) ? g_k : g_v;
    const float s = (part == 0) ? SCALE_ : 1.0f;
#pragma unroll
    for (int i = 0; i < 4; i++) {
        int r  = row0 + (ty << 2) + i;
        int bb = r >> 10, ii = r & 1023;
        float* p = dst + ((size_t)(bb * H_ + h) * N_ + ii) * D_ + (tx << 2);
        float4 o4 = make_float4(acc[i][0] * s, acc[i][1] * s,
                                acc[i][2] * s, acc[i][3] * s);
        *(float4*)p = o4;
    }
}

// ---------------------------------------------------------------------------
// Kernel 2: sim[bh] = Q[bh] @ K[bh]^T   ([1024,64]x[64,1024])
//   Tile 64(i) x 64(j), full K-dim=64, 256 thr, 4x4 microtile.
// ---------------------------------------------------------------------------
__global__ void __launch_bounds__(256) sim_gemm() {
    __shared__ __align__(16) float Qs[64][68];  // Qs[d][i]
    __shared__ __align__(16) float Ks[64][68];  // Ks[d][j]
    const int tid = threadIdx.x;
    const int tx = tid & 15, ty = tid >> 4;
    const int bh = blockIdx.z;
    const int i0 = blockIdx.y * 64, j0 = blockIdx.x * 64;
    const float* Qp = g_q + (size_t)bh * N_ * D_;
    const float* Kp = g_k + (size_t)bh * N_ * D_;
#pragma unroll
    for (int it = 0; it < 4; it++) {
        int f = tid + it * 256;
        int r = f >> 4;
        int c = (f & 15) << 2;
        float4 q4 = *(const float4*)(Qp + (size_t)(i0 + r) * D_ + c);
        Qs[c + 0][r] = q4.x; Qs[c + 1][r] = q4.y;
        Qs[c + 2][r] = q4.z; Qs[c + 3][r] = q4.w;
        float4 k4 = *(const float4*)(Kp + (size_t)(j0 + r) * D_ + c);
        Ks[c + 0][r] = k4.x; Ks[c + 1][r] = k4.y;
        Ks[c + 2][r] = k4.z; Ks[c + 3][r] = k4.w;
    }
    __syncthreads();
    float acc[4][4] = {};
#pragma unroll 16
    for (int kk = 0; kk < 64; kk++) {
        float4 a4 = *(float4*)(&Qs[kk][ty << 2]);
        float4 b4 = *(float4*)(&Ks[kk][tx << 2]);
        float av[4] = {a4.x, a4.y, a4.z, a4.w};
        float bv[4] = {b4.x, b4.y, b4.z, b4.w};
#pragma unroll
        for (int i = 0; i < 4; i++)
#pragma unroll
            for (int j = 0; j < 4; j++)
                acc[i][j] = fmaf(av[i], bv[j], acc[i][j]);
    }
    float* S = g_attn + ((size_t)bh * N_ + i0) * N_ + j0;
#pragma unroll
    for (int i = 0; i < 4; i++) {
        float4 o4 = make_float4(acc[i][0], acc[i][1], acc[i][2], acc[i][3]);
        *(float4*)(S + (size_t)((ty << 2) + i) * N_ + (tx << 2)) = o4;
    }
}

// ---------------------------------------------------------------------------
// Kernel 3: exact 1.5-entmax per row via bisection on
//   f(tau) = sum (z - tau)_+^2 - 1 = 0, z = sim/2 - max(sim/2).
//   Root bracketed in [-1, 0]; f convex & strictly decreasing. In-place.
// ---------------------------------------------------------------------------
__device__ __forceinline__ float warp_max(float v) {
#pragma unroll
    for (int o = 16; o; o >>= 1) v = fmaxf(v, __shfl_xor_sync(0xffffffffu, v, o));
    return v;
}
__device__ __forceinline__ float warp_sum(float v) {
#pragma unroll
    for (int o = 16; o; o >>= 1) v += __shfl_xor_sync(0xffffffffu, v, o);
    return v;
}

__global__ void __launch_bounds__(256) entmax_kernel() {
    __shared__ float sm[8];
    const int tid = threadIdx.x;
    const int wid = tid >> 5, lane = tid & 31;
    float* p = g_attn + (size_t)blockIdx.x * N_;

    float4 v = ((const float4*)p)[tid];
    float z0 = v.x * 0.5f, z1 = v.y * 0.5f, z2 = v.z * 0.5f, z3 = v.w * 0.5f;

    // row max
    float m = fmaxf(fmaxf(z0, z1), fmaxf(z2, z3));
    m = warp_max(m);
    if (lane == 0) sm[wid] = m;
    __syncthreads();
    m = fmaxf(fmaxf(fmaxf(sm[0], sm[1]), fmaxf(sm[2], sm[3])),
              fmaxf(fmaxf(sm[4], sm[5]), fmaxf(sm[6], sm[7])));
    __syncthreads();
    z0 -= m; z1 -= m; z2 -= m; z3 -= m;

    float lo = -1.0f, hi = 0.0f;
#pragma unroll 1
    for (int it = 0; it < 24; it++) {
        float tau = 0.5f * (lo + hi);
        float d0 = z0 - tau, d1 = z1 - tau, d2 = z2 - tau, d3 = z3 - tau;
        float s = 0.f;
        if (d0 > 0.f) s += d0 * d0;
        if (d1 > 0.f) s += d1 * d1;
        if (d2 > 0.f) s += d2 * d2;
        if (d3 > 0.f) s += d3 * d3;
        s = warp_sum(s);
        if (lane == 0) sm[wid] = s;
        __syncthreads();
        float f = ((sm[0] + sm[1]) + (sm[2] + sm[3])) +
                  ((sm[4] + sm[5]) + (sm[6] + sm[7]));
        __syncthreads();
        if (f >= 1.0f) lo = tau; else hi = tau;   // identical on all threads
    }
    const float tau = 0.5f * (lo + hi);
    float d0 = fmaxf(z0 - tau, 0.f), d1 = fmaxf(z1 - tau, 0.f);
    float d2 = fmaxf(z2 - tau, 0.f), d3 = fmaxf(z3 - tau, 0.f);
    ((float4*)p)[tid] = make_float4(d0 * d0, d1 * d1, d2 * d2, d3 * d3);
}

// ---------------------------------------------------------------------------
// Kernel 4: out[bh] = attn[bh] @ V[bh]  ([1024,1024]x[1024,64]) -> token-major
//   Tile 64(i) x 64(d), BK=32.
// ---------------------------------------------------------------------------
__global__ void __launch_bounds__(256) av_gemm() {
    __shared__ __align__(16) float As[32][68];  // As[j][i]
    __shared__ __align__(16) float Vs[32][64];  // Vs[j][d]
    const int tid = threadIdx.x;
    const int tx = tid & 15, ty = tid >> 4;
    const int bh = blockIdx.y;
    const int i0 = blockIdx.x * 64;
    const float* A = g_attn + ((size_t)bh * N_ + i0) * N_;
    const float* V = g_v + (size_t)bh * N_ * D_;

    float acc[4][4] = {};
    for (int k0 = 0; k0 < N_; k0 += 32) {
#pragma unroll
        for (int it = 0; it < 2; it++) {
            int f = tid + it * 256;
            int r = f >> 3;             // i 0..63
            int c = (f & 7) << 2;       // j 0..31
            float4 a4 = *(const float4*)(A + (size_t)r * N_ + k0 + c);
            As[c + 0][r] = a4.x; As[c + 1][r] = a4.y;
            As[c + 2][r] = a4.z; As[c + 3][r] = a4.w;
        }
#pragma unroll
        for (int it = 0; it < 2; it++) {
            int f = tid + it * 256;
            int r = f >> 4;             // j 0..31
            int c = (f & 15) << 2;      // d
            *(float4*)(&Vs[r][c]) = *(const float4*)(V + (size_t)(k0 + r) * D_ + c);
        }
        __syncthreads();
#pragma unroll
        for (int kk = 0; kk < 32; kk++) {
            float4 a4 = *(float4*)(&As[kk][ty << 2]);
            float4 b4 = *(float4*)(&Vs[kk][tx << 2]);
            float av[4] = {a4.x, a4.y, a4.z, a4.w};
            float bv[4] = {b4.x, b4.y, b4.z, b4.w};
#pragma unroll
            for (int i = 0; i < 4; i++)
#pragma unroll
                for (int j = 0; j < 4; j++)
                    acc[i][j] = fmaf(av[i], bv[j], acc[i][j]);
        }
        __syncthreads();
    }
    const int b = bh >> 3, h = bh & 7;
#pragma unroll
    for (int i = 0; i < 4; i++) {
        int ii = i0 + (ty << 2) + i;
        float* p = g_o + ((size_t)(b * N_ + ii)) * (H_ * D_) + h * D_ + (tx << 2);
        *(float4*)p = make_float4(acc[i][0], acc[i][1], acc[i][2], acc[i][3]);
    }
}

// ---------------------------------------------------------------------------
// Kernel 5: final = g_o @ w_out   (M=4096, K=512, N=512)
// ---------------------------------------------------------------------------
__global__ void __launch_bounds__(256) out_gemm(const float* __restrict__ Wo,
                                               float* __restrict__ out) {
    __shared__ __align__(16) float As[16][68];
    __shared__ __align__(16) float Bs[16][64];
    const int tid = threadIdx.x;
    const int tx = tid & 15, ty = tid >> 4;
    const int row0 = blockIdx.y * 64;
    const int col0 = blockIdx.x * 64;
    const int ar = tid >> 2, ak = (tid & 3) << 2;
    const int br = tid >> 4, bc = (tid & 15) << 2;

    float acc[4][4] = {};
    for (int k0 = 0; k0 < DIM_; k0 += 16) {
        float4 a = *(const float4*)(g_o + (size_t)(row0 + ar) * DIM_ + k0 + ak);
        As[ak + 0][ar] = a.x; As[ak + 1][ar] = a.y;
        As[ak + 2][ar] = a.z; As[ak + 3][ar] = a.w;
        *(float4*)(&Bs[br][bc]) =
            *(const float4*)(Wo + (size_t)(k0 + br) * DIM_ + col0 + bc);
        __syncthreads();
#pragma unroll
        for (int kk = 0; kk < 16; kk++) {
            float4 a4 = *(float4*)(&As[kk][ty << 2]);
            float4 b4 = *(float4*)(&Bs[kk][tx << 2]);
            float av[4] = {a4.x, a4.y, a4.z, a4.w};
            float bv[4] = {b4.x, b4.y, b4.z, b4.w};
#pragma unroll
            for (int i = 0; i < 4; i++)
#pragma unroll
                for (int j = 0; j < 4; j++)
                    acc[i][j] = fmaf(av[i], bv[j], acc[i][j]);
        }
        __syncthreads();
    }
#pragma unroll
    for (int i = 0; i < 4; i++) {
        int r = row0 + (ty << 2) + i;
        *(float4*)(out + (size_t)r * DIM_ + col0 + (tx << 2)) =
            make_float4(acc[i][0], acc[i][1], acc[i][2], acc[i][3]);
    }
}

// ---------------------------------------------------------------------------
// kernel_launch: x, w_qkv, w_out in that order (metadata.txt order)
// ---------------------------------------------------------------------------
extern "C" void kernel_launch(void* const* d_in, const int* in_sizes, int n_in,
                              void* d_out, int out_size) {
    (void)in_sizes; (void)n_in; (void)out_size;
    const float* x     = (const float*)d_in[0];
    const float* w_qkv = (const float*)d_in[1];
    const float* w_out = (const float*)d_in[2];
    float* out = (float*)d_out;

    qkv_gemm<<<dim3(1536 / 64, (B_ * N_) / 64), 256>>>(x, w_qkv);
    sim_gemm<<<dim3(N_ / 64, N_ / 64, BH_), 256>>>();
    entmax_kernel<<<BH_ * N_, 256>>>();
    av_gemm<<<dim3(N_ / 64, BH_), 256>>>();
    out_gemm<<<dim3(DIM_ / 64, (B_ * N_) / 64), 256>>>(w_out, out);
}

// round 6
// speedup vs baseline: 1.2678x; 1.2678x over previous
#include <cuda_runtime.h>
#include <cuda_bf16.h>
#include <cstdint>

#define B_   4
#define N_   1024
#define DIM_ 512
#define H_   8
#define D_   64
#define BH_  32
#define SCALE_ 0.125f
#define SMS  72      // smem tile row stride in elements (64 data + 8 pad)

// ---------------------------------------------------------------------------
// Global scratch
// ---------------------------------------------------------------------------
__device__ __nv_bfloat16 xb_hi[4096 * 512], xb_lo[4096 * 512];
__device__ __nv_bfloat16 wqkvT_hi[1536 * 512], wqkvT_lo[1536 * 512];
__device__ __nv_bfloat16 woutT_hi[512 * 512], woutT_lo[512 * 512];
__device__ __nv_bfloat16 qb_hi[BH_ * N_ * D_], qb_lo[BH_ * N_ * D_];
__device__ __nv_bfloat16 kb_hi[BH_ * N_ * D_], kb_lo[BH_ * N_ * D_];
__device__ __nv_bfloat16 vb_hi[BH_ * N_ * D_], vb_lo[BH_ * N_ * D_];
__device__ __nv_bfloat16 vbT_hi[BH_ * D_ * N_], vbT_lo[BH_ * D_ * N_];
__device__ float g_sim[(size_t)BH_ * N_ * N_];
__device__ __nv_bfloat16 ab_hi[(size_t)BH_ * N_ * N_], ab_lo[(size_t)BH_ * N_ * N_];
__device__ __nv_bfloat16 ob_hi[4096 * 512], ob_lo[4096 * 512];

// ---------------------------------------------------------------------------
// Helpers
// ---------------------------------------------------------------------------
__device__ __forceinline__ void f32split(float v, __nv_bfloat16& h, __nv_bfloat16& l) {
    h = __float2bfloat16(v);
    l = __float2bfloat16(v - __bfloat162float(h));
}
__device__ __forceinline__ uint32_t pack2(__nv_bfloat16 a, __nv_bfloat16 b) {
    return (uint32_t)__bfloat16_as_ushort(a) |
           ((uint32_t)__bfloat16_as_ushort(b) << 16);
}
__device__ __forceinline__ uint32_t packsplit(float v0, float v1,
                                              __nv_bfloat16& l0, __nv_bfloat16& l1) {
    __nv_bfloat16 h0, h1;
    f32split(v0, h0, l0); f32split(v1, h1, l1);
    return pack2(h0, h1);
}

// m16n8k16 bf16 MMA, fp32 accumulate
__device__ __forceinline__ void mma16816(float* c, const uint32_t* a, const uint32_t* b) {
    asm volatile(
        "mma.sync.aligned.m16n8k16.row.col.f32.bf16.bf16.f32 "
        "{%0,%1,%2,%3}, {%4,%5,%6,%7}, {%8,%9}, {%0,%1,%2,%3};"
        : "+f"(c[0]), "+f"(c[1]), "+f"(c[2]), "+f"(c[3])
        : "r"(a[0]), "r"(a[1]), "r"(a[2]), "r"(a[3]), "r"(b[0]), "r"(b[1]));
}

// Load A fragment (m16k16) from K-major smem tile, row stride SMS
__device__ __forceinline__ void ldA(uint32_t* a, const __nv_bfloat16* As,
                                    int m0, int k0, int g, int q) {
    a[0] = *(const uint32_t*)(As + (m0 + g) * SMS + k0 + q * 2);
    a[1] = *(const uint32_t*)(As + (m0 + g + 8) * SMS + k0 + q * 2);
    a[2] = *(const uint32_t*)(As + (m0 + g) * SMS + k0 + 8 + q * 2);
    a[3] = *(const uint32_t*)(As + (m0 + g + 8) * SMS + k0 + 8 + q * 2);
}
// Load B fragment (k16n8) from K-major ([n][k]) smem tile
__device__ __forceinline__ void ldB(uint32_t* b, const __nv_bfloat16* Bs,
                                    int n0, int k0, int g, int q) {
    b[0] = *(const uint32_t*)(Bs + (n0 + g) * SMS + k0 + q * 2);
    b[1] = *(const uint32_t*)(Bs + (n0 + g) * SMS + k0 + 8 + q * 2);
}

// Fill a [rows x 64] bf16 tile into smem (stride SMS), coalesced uint4
__device__ __forceinline__ void load_tile(__nv_bfloat16* dst, const __nv_bfloat16* g,
                                          int rows, int gstride, int tid) {
    for (int i = tid; i < rows * 8; i += 256) {
        int r = i >> 3, q = i & 7;
        *(uint4*)(dst + r * SMS + q * 8) = *(const uint4*)(g + (size_t)r * gstride + q * 8);
    }
}

// ---------------------------------------------------------------------------
// Conversion prologue
// ---------------------------------------------------------------------------
__global__ void __launch_bounds__(256) conv_x(const float* __restrict__ x) {
    int i = blockIdx.x * 256 + threadIdx.x;   // < 524288
    float4 v = ((const float4*)x)[i];
    __nv_bfloat16 l0, l1, l2, l3;
    uint32_t h01 = packsplit(v.x, v.y, l0, l1);
    uint32_t h23 = packsplit(v.z, v.w, l2, l3);
    *(uint2*)(xb_hi + (size_t)i * 4) = make_uint2(h01, h23);
    *(uint2*)(xb_lo + (size_t)i * 4) = make_uint2(pack2(l0, l1), pack2(l2, l3));
}

__global__ void __launch_bounds__(256) conv_w(const float* __restrict__ w,
                                              __nv_bfloat16* th, __nv_bfloat16* tl,
                                              int cols) {
    int i = blockIdx.x * 256 + threadIdx.x;       // i = n*512 + k
    int n = i >> 9, k = i & 511;
    float v = w[(size_t)k * cols + n];
    __nv_bfloat16 h, l;
    f32split(v, h, l);
    th[i] = h; tl[i] = l;
}

// ---------------------------------------------------------------------------
// qkv = x @ w_qkv  (M=4096, N=1536, K=512) -> Q/K/V bf16 hi/lo head-major
// CTA 128x128, 8 warps (2x4), warp tile 64x32, K chunks of 64
// ---------------------------------------------------------------------------
#define GEMM_SMEM (4 * 128 * SMS * 2)   // 73728 B

__global__ void __launch_bounds__(256) qkv_mma() {
    extern __shared__ __nv_bfloat16 smp[];
    __nv_bfloat16 *AH = smp, *AL = smp + 128 * SMS,
                  *BHs = smp + 2 * 128 * SMS, *BLs = smp + 3 * 128 * SMS;
    const int tid = threadIdx.x, wid = tid >> 5, lane = tid & 31;
    const int g = lane >> 2, q = lane & 3;
    const int row0 = blockIdx.y * 128, col0 = blockIdx.x * 128;
    const int wm0 = (wid >> 2) * 64, wn0 = (wid & 3) * 32;

    float c[4][4][4] = {};
    for (int ch = 0; ch < 8; ch++) {
        load_tile(AH, xb_hi + (size_t)row0 * 512 + ch * 64, 128, 512, tid);
        load_tile(AL, xb_lo + (size_t)row0 * 512 + ch * 64, 128, 512, tid);
        load_tile(BHs, wqkvT_hi + (size_t)col0 * 512 + ch * 64, 128, 512, tid);
        load_tile(BLs, wqkvT_lo + (size_t)col0 * 512 + ch * 64, 128, 512, tid);
        __syncthreads();
#pragma unroll
        for (int k0 = 0; k0 < 64; k0 += 16) {
            uint32_t aH[4][4], aL[4][4], bH[4][2], bL[4][2];
#pragma unroll
            for (int mf = 0; mf < 4; mf++) {
                ldA(aH[mf], AH, wm0 + mf * 16, k0, g, q);
                ldA(aL[mf], AL, wm0 + mf * 16, k0, g, q);
            }
#pragma unroll
            for (int nf = 0; nf < 4; nf++) {
                ldB(bH[nf], BHs, wn0 + nf * 8, k0, g, q);
                ldB(bL[nf], BLs, wn0 + nf * 8, k0, g, q);
            }
#pragma unroll
            for (int mf = 0; mf < 4; mf++)
#pragma unroll
                for (int nf = 0; nf < 4; nf++) {
                    mma16816(c[mf][nf], aH[mf], bH[nf]);
                    mma16816(c[mf][nf], aH[mf], bL[nf]);
                    mma16816(c[mf][nf], aL[mf], bH[nf]);
                }
        }
        __syncthreads();
    }
    // epilogue: scatter to q/k/v hi/lo, head-major [bh][n][d]
    const int part = col0 >> 9;
    __nv_bfloat16* dh = part == 0 ? qb_hi : part == 1 ? kb_hi : vb_hi;
    __nv_bfloat16* dl = part == 0 ? qb_lo : part == 1 ? kb_lo : vb_lo;
    const float sc = part == 0 ? SCALE_ : 1.0f;
#pragma unroll
    for (int mf = 0; mf < 4; mf++)
#pragma unroll
        for (int nf = 0; nf < 4; nf++) {
            int ncol = (col0 & 511) + wn0 + nf * 8 + q * 2;
            int head = ncol >> 6, d = ncol & 63;
#pragma unroll
            for (int half = 0; half < 2; half++) {
                int m = row0 + wm0 + mf * 16 + g + half * 8;
                __nv_bfloat16 l0, l1;
                uint32_t hp = packsplit(c[mf][nf][half * 2] * sc,
                                        c[mf][nf][half * 2 + 1] * sc, l0, l1);
                size_t base = ((size_t)((m >> 10) * 8 + head) * 1024 + (m & 1023)) * 64 + d;
                *(uint32_t*)(dh + base) = hp;
                *(uint32_t*)(dl + base) = pack2(l0, l1);
            }
        }
}

// ---------------------------------------------------------------------------
// V transpose: vb [bh][j][d] -> vbT [bh][d][j]
// ---------------------------------------------------------------------------
__global__ void __launch_bounds__(256) vtrans() {
    __shared__ __nv_bfloat16 th[32][33], tl[32][33];
    const int bh = blockIdx.z, j0 = blockIdx.x * 32, d0 = blockIdx.y * 32;
    const int tx = threadIdx.x & 31, ty = threadIdx.x >> 5;
    const size_t src = ((size_t)bh * 1024 + j0) * 64 + d0;
    for (int r = ty; r < 32; r += 8) {
        th[r][tx] = vb_hi[src + (size_t)r * 64 + tx];
        tl[r][tx] = vb_lo[src + (size_t)r * 64 + tx];
    }
    __syncthreads();
    const size_t dst = ((size_t)bh * 64 + d0) * 1024 + j0;
    for (int r = ty; r < 32; r += 8) {
        vbT_hi[dst + (size_t)r * 1024 + tx] = th[tx][r];
        vbT_lo[dst + (size_t)r * 1024 + tx] = tl[tx][r];
    }
}

// ---------------------------------------------------------------------------
// sim = Q @ K^T per bh.  CTA 128x128, K=64 (one tile), fp32 out
// ---------------------------------------------------------------------------
__global__ void __launch_bounds__(256) sim_mma() {
    extern __shared__ __nv_bfloat16 smp[];
    __nv_bfloat16 *QH = smp, *QL = smp + 128 * SMS,
                  *KH = smp + 2 * 128 * SMS, *KL = smp + 3 * 128 * SMS;
    const int tid = threadIdx.x, wid = tid >> 5, lane = tid & 31;
    const int g = lane >> 2, q = lane & 3;
    const int j0 = blockIdx.x * 128, i0 = blockIdx.y * 128, bh = blockIdx.z;
    const int wm0 = (wid >> 2) * 64, wn0 = (wid & 3) * 32;

    load_tile(QH, qb_hi + ((size_t)(bh << 10) + i0) * 64, 128, 64, tid);
    load_tile(QL, qb_lo + ((size_t)(bh << 10) + i0) * 64, 128, 64, tid);
    load_tile(KH, kb_hi + ((size_t)(bh << 10) + j0) * 64, 128, 64, tid);
    load_tile(KL, kb_lo + ((size_t)(bh << 10) + j0) * 64, 128, 64, tid);
    __syncthreads();

    float c[4][4][4] = {};
#pragma unroll
    for (int k0 = 0; k0 < 64; k0 += 16) {
        uint32_t aH[4][4], aL[4][4], bH[4][2], bL[4][2];
#pragma unroll
        for (int mf = 0; mf < 4; mf++) {
            ldA(aH[mf], QH, wm0 + mf * 16, k0, g, q);
            ldA(aL[mf], QL, wm0 + mf * 16, k0, g, q);
        }
#pragma unroll
        for (int nf = 0; nf < 4; nf++) {
            ldB(bH[nf], KH, wn0 + nf * 8, k0, g, q);
            ldB(bL[nf], KL, wn0 + nf * 8, k0, g, q);
        }
#pragma unroll
        for (int mf = 0; mf < 4; mf++)
#pragma unroll
            for (int nf = 0; nf < 4; nf++) {
                mma16816(c[mf][nf], aH[mf], bH[nf]);
                mma16816(c[mf][nf], aH[mf], bL[nf]);
                mma16816(c[mf][nf], aL[mf], bH[nf]);
            }
    }
#pragma unroll
    for (int mf = 0; mf < 4; mf++)
#pragma unroll
        for (int nf = 0; nf < 4; nf++) {
            int j = j0 + wn0 + nf * 8 + q * 2;
#pragma unroll
            for (int half = 0; half < 2; half++) {
                int i = i0 + wm0 + mf * 16 + g + half * 8;
                *(float2*)(g_sim + ((size_t)(bh << 10) + i) * 1024 + j) =
                    make_float2(c[mf][nf][half * 2], c[mf][nf][half * 2 + 1]);
            }
        }
}

// ---------------------------------------------------------------------------
// entmax-1.5 per row (bisection) -> attn bf16 hi/lo
// ---------------------------------------------------------------------------
__device__ __forceinline__ float warp_max(float v) {
#pragma unroll
    for (int o = 16; o; o >>= 1) v = fmaxf(v, __shfl_xor_sync(0xffffffffu, v, o));
    return v;
}
__device__ __forceinline__ float warp_sum(float v) {
#pragma unroll
    for (int o = 16; o; o >>= 1) v += __shfl_xor_sync(0xffffffffu, v, o);
    return v;
}

__global__ void __launch_bounds__(256) entmax_k() {
    __shared__ float sm[8];
    const int tid = threadIdx.x, wid = tid >> 5, lane = tid & 31;
    const size_t row = blockIdx.x;
    const float4 v = ((const float4*)(g_sim + row * 1024))[tid];
    float z0 = v.x * 0.5f, z1 = v.y * 0.5f, z2 = v.z * 0.5f, z3 = v.w * 0.5f;

    float m = fmaxf(fmaxf(z0, z1), fmaxf(z2, z3));
    m = warp_max(m);
    if (lane == 0) sm[wid] = m;
    __syncthreads();
    m = fmaxf(fmaxf(fmaxf(sm[0], sm[1]), fmaxf(sm[2], sm[3])),
              fmaxf(fmaxf(sm[4], sm[5]), fmaxf(sm[6], sm[7])));
    __syncthreads();
    z0 -= m; z1 -= m; z2 -= m; z3 -= m;

    float lo = -1.0f, hi = 0.0f;
#pragma unroll 1
    for (int it = 0; it < 20; it++) {
        float tau = 0.5f * (lo + hi);
        float d0 = z0 - tau, d1 = z1 - tau, d2 = z2 - tau, d3 = z3 - tau;
        float ss = 0.f;
        if (d0 > 0.f) ss += d0 * d0;
        if (d1 > 0.f) ss += d1 * d1;
        if (d2 > 0.f) ss += d2 * d2;
        if (d3 > 0.f) ss += d3 * d3;
        ss = warp_sum(ss);
        if (lane == 0) sm[wid] = ss;
        __syncthreads();
        float f = ((sm[0] + sm[1]) + (sm[2] + sm[3])) +
                  ((sm[4] + sm[5]) + (sm[6] + sm[7]));
        __syncthreads();
        if (f >= 1.0f) lo = tau; else hi = tau;
    }
    const float tau = 0.5f * (lo + hi);
    float a0 = fmaxf(z0 - tau, 0.f), a1 = fmaxf(z1 - tau, 0.f);
    float a2 = fmaxf(z2 - tau, 0.f), a3 = fmaxf(z3 - tau, 0.f);
    a0 *= a0; a1 *= a1; a2 *= a2; a3 *= a3;
    __nv_bfloat16 l0, l1, l2, l3;
    uint32_t h01 = packsplit(a0, a1, l0, l1);
    uint32_t h23 = packsplit(a2, a3, l2, l3);
    size_t base = row * 1024 + (size_t)tid * 4;
    *(uint2*)(ab_hi + base) = make_uint2(h01, h23);
    *(uint2*)(ab_lo + base) = make_uint2(pack2(l0, l1), pack2(l2, l3));
}

// ---------------------------------------------------------------------------
// out = attn @ V per bh.  CTA 128(i) x 64(d), warp tile 32x32, K=1024/64
// ---------------------------------------------------------------------------
#define AV_SMEM ((2 * 128 + 2 * 64) * SMS * 2)   // 55296 B

__global__ void __launch_bounds__(256) av_mma() {
    extern __shared__ __nv_bfloat16 smp[];
    __nv_bfloat16 *AH = smp, *AL = smp + 128 * SMS,
                  *BHs = smp + 2 * 128 * SMS, *BLs = smp + 2 * 128 * SMS + 64 * SMS;
    const int tid = threadIdx.x, wid = tid >> 5, lane = tid & 31;
    const int g = lane >> 2, q = lane & 3;
    const int i0 = blockIdx.x * 128, bh = blockIdx.y;
    const int wm0 = (wid >> 1) * 32, wn0 = (wid & 1) * 32;

    float c[2][4][4] = {};
    for (int ch = 0; ch < 16; ch++) {
        load_tile(AH, ab_hi + ((size_t)(bh << 10) + i0) * 1024 + ch * 64, 128, 1024, tid);
        load_tile(AL, ab_lo + ((size_t)(bh << 10) + i0) * 1024 + ch * 64, 128, 1024, tid);
        load_tile(BHs, vbT_hi + ((size_t)bh * 64) * 1024 + ch * 64, 64, 1024, tid);
        load_tile(BLs, vbT_lo + ((size_t)bh * 64) * 1024 + ch * 64, 64, 1024, tid);
        __syncthreads();
#pragma unroll
        for (int k0 = 0; k0 < 64; k0 += 16) {
            uint32_t aH[2][4], aL[2][4], bH[4][2], bL[4][2];
#pragma unroll
            for (int mf = 0; mf < 2; mf++) {
                ldA(aH[mf], AH, wm0 + mf * 16, k0, g, q);
                ldA(aL[mf], AL, wm0 + mf * 16, k0, g, q);
            }
#pragma unroll
            for (int nf = 0; nf < 4; nf++) {
                ldB(bH[nf], BHs, wn0 + nf * 8, k0, g, q);
                ldB(bL[nf], BLs, wn0 + nf * 8, k0, g, q);
            }
#pragma unroll
            for (int mf = 0; mf < 2; mf++)
#pragma unroll
                for (int nf = 0; nf < 4; nf++) {
                    mma16816(c[mf][nf], aH[mf], bH[nf]);
                    mma16816(c[mf][nf], aH[mf], bL[nf]);
                    mma16816(c[mf][nf], aL[mf], bH[nf]);
                }
        }
        __syncthreads();
    }
    // epilogue -> ob hi/lo, token-major [b*1024+i][h*64+d]
    const int b = bh >> 3, h = bh & 7;
#pragma unroll
    for (int mf = 0; mf < 2; mf++)
#pragma unroll
        for (int nf = 0; nf < 4; nf++) {
            int d = wn0 + nf * 8 + q * 2;
#pragma unroll
            for (int half = 0; half < 2; half++) {
                int i = i0 + wm0 + mf * 16 + g + half * 8;
                __nv_bfloat16 l0, l1;
                uint32_t hp = packsplit(c[mf][nf][half * 2],
                                        c[mf][nf][half * 2 + 1], l0, l1);
                size_t base = ((size_t)b * 1024 + i) * 512 + h * 64 + d;
                *(uint32_t*)(ob_hi + base) = hp;
                *(uint32_t*)(ob_lo + base) = pack2(l0, l1);
            }
        }
}

// ---------------------------------------------------------------------------
// final = o @ w_out  (M=4096, N=512, K=512) -> fp32 d_out
// ---------------------------------------------------------------------------
__global__ void __launch_bounds__(256) out_mma(float* __restrict__ out) {
    extern __shared__ __nv_bfloat16 smp[];
    __nv_bfloat16 *AH = smp, *AL = smp + 128 * SMS,
                  *BHs = smp + 2 * 128 * SMS, *BLs = smp + 3 * 128 * SMS;
    const int tid = threadIdx.x, wid = tid >> 5, lane = tid & 31;
    const int g = lane >> 2, q = lane & 3;
    const int row0 = blockIdx.y * 128, col0 = blockIdx.x * 128;
    const int wm0 = (wid >> 2) * 64, wn0 = (wid & 3) * 32;

    float c[4][4][4] = {};
    for (int ch = 0; ch < 8; ch++) {
        load_tile(AH, ob_hi + (size_t)row0 * 512 + ch * 64, 128, 512, tid);
        load_tile(AL, ob_lo + (size_t)row0 * 512 + ch * 64, 128, 512, tid);
        load_tile(BHs, woutT_hi + (size_t)col0 * 512 + ch * 64, 128, 512, tid);
        load_tile(BLs, woutT_lo + (size_t)col0 * 512 + ch * 64, 128, 512, tid);
        __syncthreads();
#pragma unroll
        for (int k0 = 0; k0 < 64; k0 += 16) {
            uint32_t aH[4][4], aL[4][4], bH[4][2], bL[4][2];
#pragma unroll
            for (int mf = 0; mf < 4; mf++) {
                ldA(aH[mf], AH, wm0 + mf * 16, k0, g, q);
                ldA(aL[mf], AL, wm0 + mf * 16, k0, g, q);
            }
#pragma unroll
            for (int nf = 0; nf < 4; nf++) {
                ldB(bH[nf], BHs, wn0 + nf * 8, k0, g, q);
                ldB(bL[nf], BLs, wn0 + nf * 8, k0, g, q);
            }
#pragma unroll
            for (int mf = 0; mf < 4; mf++)
#pragma unroll
                for (int nf = 0; nf < 4; nf++) {
                    mma16816(c[mf][nf], aH[mf], bH[nf]);
                    mma16816(c[mf][nf], aH[mf], bL[nf]);
                    mma16816(c[mf][nf], aL[mf], bH[nf]);
                }
        }
        __syncthreads();
    }
#pragma unroll
    for (int mf = 0; mf < 4; mf++)
#pragma unroll
        for (int nf = 0; nf < 4; nf++) {
            int n = col0 + wn0 + nf * 8 + q * 2;
#pragma unroll
            for (int half = 0; half < 2; half++) {
                int m = row0 + wm0 + mf * 16 + g + half * 8;
                *(float2*)(out + (size_t)m * 512 + n) =
                    make_float2(c[mf][nf][half * 2], c[mf][nf][half * 2 + 1]);
            }
        }
}

// ---------------------------------------------------------------------------
// kernel_launch
// ---------------------------------------------------------------------------
extern "C" void kernel_launch(void* const* d_in, const int* in_sizes, int n_in,
                              void* d_out, int out_size) {
    (void)in_sizes; (void)n_in; (void)out_size;
    const float* x     = (const float*)d_in[0];
    const float* w_qkv = (const float*)d_in[1];
    const float* w_out = (const float*)d_in[2];
    float* out = (float*)d_out;

    cudaFuncSetAttribute(qkv_mma, cudaFuncAttributeMaxDynamicSharedMemorySize, GEMM_SMEM);
    cudaFuncSetAttribute(sim_mma, cudaFuncAttributeMaxDynamicSharedMemorySize, GEMM_SMEM);
    cudaFuncSetAttribute(av_mma,  cudaFuncAttributeMaxDynamicSharedMemorySize, AV_SMEM);
    cudaFuncSetAttribute(out_mma, cudaFuncAttributeMaxDynamicSharedMemorySize, GEMM_SMEM);

    __nv_bfloat16 *wqh, *wql, *woh, *wol;
    cudaGetSymbolAddress((void**)&wqh, wqkvT_hi);
    cudaGetSymbolAddress((void**)&wql, wqkvT_lo);
    cudaGetSymbolAddress((void**)&woh, woutT_hi);
    cudaGetSymbolAddress((void**)&wol, woutT_lo);

    conv_x<<<2048, 256>>>(x);
    conv_w<<<3072, 256>>>(w_qkv, wqh, wql, 1536);
    conv_w<<<1024, 256>>>(w_out, woh, wol, 512);
    qkv_mma<<<dim3(12, 32), 256, GEMM_SMEM>>>();
    vtrans<<<dim3(32, 2, 32), 256>>>();
    sim_mma<<<dim3(8, 8, 32), 256, GEMM_SMEM>>>();
    entmax_k<<<BH_ * N_, 256>>>();
    av_mma<<<dim3(8, 32), 256, AV_SMEM>>>();
    out_mma<<<dim3(4, 32), 256, GEMM_SMEM>>>(out);
}

// round 7
// speedup vs baseline: 1.7186x; 1.3556x over previous
#include <cuda_runtime.h>
#include <cuda_bf16.h>
#include <cstdint>

#define B_   4
#define N_   1024
#define DIM_ 512
#define H_   8
#define D_   64
#define BH_  32
#define SCALE_ 0.125f
#define SMS  72      // smem tile row stride in elements (64 data + 8 pad)
#define TILE_E (128 * SMS)   // elements in a 128-row tile
#define BTILE_E (64 * SMS)   // elements in a 64-row tile

// ---------------------------------------------------------------------------
// Global scratch
// ---------------------------------------------------------------------------
__device__ __nv_bfloat16 xb_hi[4096 * 512], xb_lo[4096 * 512];
__device__ __nv_bfloat16 wqkvT_hi[1536 * 512], wqkvT_lo[1536 * 512];
__device__ __nv_bfloat16 woutT_hi[512 * 512], woutT_lo[512 * 512];
__device__ __nv_bfloat16 qb_hi[BH_ * N_ * D_], qb_lo[BH_ * N_ * D_];
__device__ __nv_bfloat16 kb_hi[BH_ * N_ * D_], kb_lo[BH_ * N_ * D_];
__device__ __nv_bfloat16 vb_hi[BH_ * N_ * D_], vb_lo[BH_ * N_ * D_];
__device__ __nv_bfloat16 vbT_hi[BH_ * D_ * N_], vbT_lo[BH_ * D_ * N_];
__device__ float g_sim[(size_t)BH_ * N_ * N_];
__device__ __nv_bfloat16 ab_hi[(size_t)BH_ * N_ * N_], ab_lo[(size_t)BH_ * N_ * N_];
__device__ __nv_bfloat16 ob_hi[4096 * 512], ob_lo[4096 * 512];

// ---------------------------------------------------------------------------
// Helpers
// ---------------------------------------------------------------------------
__device__ __forceinline__ void f32split(float v, __nv_bfloat16& h, __nv_bfloat16& l) {
    h = __float2bfloat16(v);
    l = __float2bfloat16(v - __bfloat162float(h));
}
__device__ __forceinline__ uint32_t pack2(__nv_bfloat16 a, __nv_bfloat16 b) {
    return (uint32_t)__bfloat16_as_ushort(a) |
           ((uint32_t)__bfloat16_as_ushort(b) << 16);
}
__device__ __forceinline__ uint32_t packsplit(float v0, float v1,
                                              __nv_bfloat16& l0, __nv_bfloat16& l1) {
    __nv_bfloat16 h0, h1;
    f32split(v0, h0, l0); f32split(v1, h1, l1);
    return pack2(h0, h1);
}

__device__ __forceinline__ void mma16816(float* c, const uint32_t* a, const uint32_t* b) {
    asm volatile(
        "mma.sync.aligned.m16n8k16.row.col.f32.bf16.bf16.f32 "
        "{%0,%1,%2,%3}, {%4,%5,%6,%7}, {%8,%9}, {%0,%1,%2,%3};"
        : "+f"(c[0]), "+f"(c[1]), "+f"(c[2]), "+f"(c[3])
        : "r"(a[0]), "r"(a[1]), "r"(a[2]), "r"(a[3]), "r"(b[0]), "r"(b[1]));
}

__device__ __forceinline__ void ldA(uint32_t* a, const __nv_bfloat16* As,
                                    int m0, int k0, int g, int q) {
    a[0] = *(const uint32_t*)(As + (m0 + g) * SMS + k0 + q * 2);
    a[1] = *(const uint32_t*)(As + (m0 + g + 8) * SMS + k0 + q * 2);
    a[2] = *(const uint32_t*)(As + (m0 + g) * SMS + k0 + 8 + q * 2);
    a[3] = *(const uint32_t*)(As + (m0 + g + 8) * SMS + k0 + 8 + q * 2);
}
__device__ __forceinline__ void ldB(uint32_t* b, const __nv_bfloat16* Bs,
                                    int n0, int k0, int g, int q) {
    b[0] = *(const uint32_t*)(Bs + (n0 + g) * SMS + k0 + q * 2);
    b[1] = *(const uint32_t*)(Bs + (n0 + g) * SMS + k0 + 8 + q * 2);
}

// cp.async 16B copy gmem -> smem
__device__ __forceinline__ void cpa16(__nv_bfloat16* dst, const __nv_bfloat16* src) {
    uint32_t s;
    asm("{ .reg .u64 t; cvta.to.shared.u64 t, %1; cvt.u32.u64 %0, t; }"
        : "=r"(s) : "l"(dst));
    asm volatile("cp.async.cg.shared.global [%0], [%1], 16;" :: "r"(s), "l"(src));
}
#define CP_COMMIT() asm volatile("cp.async.commit_group;" ::: "memory")
#define CP_WAIT0()  asm volatile("cp.async.wait_group 0;" ::: "memory")
#define CP_WAIT1()  asm volatile("cp.async.wait_group 1;" ::: "memory")

// async fill of a [rows x 64] bf16 tile into smem (stride SMS)
__device__ __forceinline__ void tile_async(__nv_bfloat16* dst, const __nv_bfloat16* g,
                                           int rows, int gstride, int tid) {
    for (int i = tid; i < rows * 8; i += 256) {
        int r = i >> 3, q = i & 7;
        cpa16(dst + r * SMS + q * 8, g + (size_t)r * gstride + q * 8);
    }
}

// ---------------------------------------------------------------------------
// Conversion prologue
// ---------------------------------------------------------------------------
__global__ void __launch_bounds__(256) conv_x(const float* __restrict__ x) {
    int i = blockIdx.x * 256 + threadIdx.x;
    float4 v = ((const float4*)x)[i];
    __nv_bfloat16 l0, l1, l2, l3;
    uint32_t h01 = packsplit(v.x, v.y, l0, l1);
    uint32_t h23 = packsplit(v.z, v.w, l2, l3);
    *(uint2*)(xb_hi + (size_t)i * 4) = make_uint2(h01, h23);
    *(uint2*)(xb_lo + (size_t)i * 4) = make_uint2(pack2(l0, l1), pack2(l2, l3));
}

__global__ void __launch_bounds__(256) conv_w(const float* __restrict__ w,
                                              __nv_bfloat16* th, __nv_bfloat16* tl,
                                              int cols) {
    int i = blockIdx.x * 256 + threadIdx.x;       // i = n*512 + k
    int n = i >> 9, k = i & 511;
    float v = w[(size_t)k * cols + n];
    __nv_bfloat16 h, l;
    f32split(v, h, l);
    th[i] = h; tl[i] = l;
}

// ---------------------------------------------------------------------------
// qkv = x @ w_qkv  (M=4096, N=1536, K=512): 2-stage cp.async pipeline
// CTA 128x128, 8 warps, warp tile 64x32, K chunks of 64
// ---------------------------------------------------------------------------
#define STAGE4_E (4 * TILE_E)
#define QKV_SMEM (2 * STAGE4_E * 2)    // 147456 B

__device__ __forceinline__ void qkv_load_chunk(__nv_bfloat16* st,
                                               const __nv_bfloat16* aH, const __nv_bfloat16* aL,
                                               const __nv_bfloat16* bH, const __nv_bfloat16* bL,
                                               int tid) {
    tile_async(st + 0 * TILE_E, aH, 128, 512, tid);
    tile_async(st + 1 * TILE_E, aL, 128, 512, tid);
    tile_async(st + 2 * TILE_E, bH, 128, 512, tid);
    tile_async(st + 3 * TILE_E, bL, 128, 512, tid);
}

__device__ __forceinline__ void gemm_compute_128(float c[4][4][4], const __nv_bfloat16* st,
                                                 int wm0, int wn0, int g, int q) {
    const __nv_bfloat16 *AH = st, *AL = st + TILE_E,
                        *BHs = st + 2 * TILE_E, *BLs = st + 3 * TILE_E;
#pragma unroll
    for (int k0 = 0; k0 < 64; k0 += 16) {
        uint32_t aH[4][4], aL[4][4], bH[4][2], bL[4][2];
#pragma unroll
        for (int mf = 0; mf < 4; mf++) {
            ldA(aH[mf], AH, wm0 + mf * 16, k0, g, q);
            ldA(aL[mf], AL, wm0 + mf * 16, k0, g, q);
        }
#pragma unroll
        for (int nf = 0; nf < 4; nf++) {
            ldB(bH[nf], BHs, wn0 + nf * 8, k0, g, q);
            ldB(bL[nf], BLs, wn0 + nf * 8, k0, g, q);
        }
#pragma unroll
        for (int mf = 0; mf < 4; mf++)
#pragma unroll
            for (int nf = 0; nf < 4; nf++) {
                mma16816(c[mf][nf], aH[mf], bH[nf]);
                mma16816(c[mf][nf], aH[mf], bL[nf]);
                mma16816(c[mf][nf], aL[mf], bH[nf]);
            }
    }
}

__global__ void __launch_bounds__(256) qkv_mma() {
    extern __shared__ __nv_bfloat16 smp[];
    const int tid = threadIdx.x, wid = tid >> 5, lane = tid & 31;
    const int g = lane >> 2, q = lane & 3;
    const int row0 = blockIdx.y * 128, col0 = blockIdx.x * 128;
    const int wm0 = (wid >> 2) * 64, wn0 = (wid & 3) * 32;

    const __nv_bfloat16* gah = xb_hi + (size_t)row0 * 512;
    const __nv_bfloat16* gal = xb_lo + (size_t)row0 * 512;
    const __nv_bfloat16* gbh = wqkvT_hi + (size_t)col0 * 512;
    const __nv_bfloat16* gbl = wqkvT_lo + (size_t)col0 * 512;

    qkv_load_chunk(smp, gah, gal, gbh, gbl, tid);
    CP_COMMIT();

    float c[4][4][4] = {};
    for (int ch = 0; ch < 8; ch++) {
        if (ch + 1 < 8) {
            __nv_bfloat16* nst = smp + ((ch + 1) & 1) * STAGE4_E;
            qkv_load_chunk(nst, gah + (ch + 1) * 64, gal + (ch + 1) * 64,
                           gbh + (ch + 1) * 64, gbl + (ch + 1) * 64, tid);
            CP_COMMIT();
            CP_WAIT1();
        } else {
            CP_WAIT0();
        }
        __syncthreads();
        gemm_compute_128(c, smp + (ch & 1) * STAGE4_E, wm0, wn0, g, q);
        __syncthreads();
    }

    const int part = col0 >> 9;
    __nv_bfloat16* dh = part == 0 ? qb_hi : part == 1 ? kb_hi : vb_hi;
    __nv_bfloat16* dl = part == 0 ? qb_lo : part == 1 ? kb_lo : vb_lo;
    const float sc = part == 0 ? SCALE_ : 1.0f;
#pragma unroll
    for (int mf = 0; mf < 4; mf++)
#pragma unroll
        for (int nf = 0; nf < 4; nf++) {
            int ncol = (col0 & 511) + wn0 + nf * 8 + q * 2;
            int head = ncol >> 6, d = ncol & 63;
#pragma unroll
            for (int half = 0; half < 2; half++) {
                int m = row0 + wm0 + mf * 16 + g + half * 8;
                __nv_bfloat16 l0, l1;
                uint32_t hp = packsplit(c[mf][nf][half * 2] * sc,
                                        c[mf][nf][half * 2 + 1] * sc, l0, l1);
                size_t base = ((size_t)((m >> 10) * 8 + head) * 1024 + (m & 1023)) * 64 + d;
                *(uint32_t*)(dh + base) = hp;
                *(uint32_t*)(dl + base) = pack2(l0, l1);
            }
        }
}

// ---------------------------------------------------------------------------
// V transpose
// ---------------------------------------------------------------------------
__global__ void __launch_bounds__(256) vtrans() {
    __shared__ __nv_bfloat16 th[32][33], tl[32][33];
    const int bh = blockIdx.z, j0 = blockIdx.x * 32, d0 = blockIdx.y * 32;
    const int tx = threadIdx.x & 31, ty = threadIdx.x >> 5;
    const size_t src = ((size_t)bh * 1024 + j0) * 64 + d0;
    for (int r = ty; r < 32; r += 8) {
        th[r][tx] = vb_hi[src + (size_t)r * 64 + tx];
        tl[r][tx] = vb_lo[src + (size_t)r * 64 + tx];
    }
    __syncthreads();
    const size_t dst = ((size_t)bh * 64 + d0) * 1024 + j0;
    for (int r = ty; r < 32; r += 8) {
        vbT_hi[dst + (size_t)r * 1024 + tx] = th[tx][r];
        vbT_lo[dst + (size_t)r * 1024 + tx] = tl[tx][r];
    }
}

// ---------------------------------------------------------------------------
// sim = Q @ K^T per bh.  CTA 128x128, K=64 single chunk, 2 CTAs/SM
// ---------------------------------------------------------------------------
#define SIM_SMEM (STAGE4_E * 2)        // 73728 B

__global__ void __launch_bounds__(256, 2) sim_mma() {
    extern __shared__ __nv_bfloat16 smp[];
    const int tid = threadIdx.x, wid = tid >> 5, lane = tid & 31;
    const int g = lane >> 2, q = lane & 3;
    const int j0 = blockIdx.x * 128, i0 = blockIdx.y * 128, bh = blockIdx.z;
    const int wm0 = (wid >> 2) * 64, wn0 = (wid & 3) * 32;

    tile_async(smp + 0 * TILE_E, qb_hi + ((size_t)(bh << 10) + i0) * 64, 128, 64, tid);
    tile_async(smp + 1 * TILE_E, qb_lo + ((size_t)(bh << 10) + i0) * 64, 128, 64, tid);
    tile_async(smp + 2 * TILE_E, kb_hi + ((size_t)(bh << 10) + j0) * 64, 128, 64, tid);
    tile_async(smp + 3 * TILE_E, kb_lo + ((size_t)(bh << 10) + j0) * 64, 128, 64, tid);
    CP_COMMIT();
    CP_WAIT0();
    __syncthreads();

    float c[4][4][4] = {};
    gemm_compute_128(c, smp, wm0, wn0, g, q);

#pragma unroll
    for (int mf = 0; mf < 4; mf++)
#pragma unroll
        for (int nf = 0; nf < 4; nf++) {
            int j = j0 + wn0 + nf * 8 + q * 2;
#pragma unroll
            for (int half = 0; half < 2; half++) {
                int i = i0 + wm0 + mf * 16 + g + half * 8;
                *(float2*)(g_sim + ((size_t)(bh << 10) + i) * 1024 + j) =
                    make_float2(c[mf][nf][half * 2], c[mf][nf][half * 2 + 1]);
            }
        }
}

// ---------------------------------------------------------------------------
// entmax-1.5 per row: monotone Newton on f(tau) = sum (z-tau)_+^2 - 1
// ---------------------------------------------------------------------------
__device__ __forceinline__ float warp_max(float v) {
#pragma unroll
    for (int o = 16; o; o >>= 1) v = fmaxf(v, __shfl_xor_sync(0xffffffffu, v, o));
    return v;
}
__device__ __forceinline__ float warp_sum(float v) {
#pragma unroll
    for (int o = 16; o; o >>= 1) v += __shfl_xor_sync(0xffffffffu, v, o);
    return v;
}

__global__ void __launch_bounds__(256) entmax_k() {
    __shared__ float sm1[8], sm2[8];
    const int tid = threadIdx.x, wid = tid >> 5, lane = tid & 31;
    const size_t row = blockIdx.x;
    const float4 v = ((const float4*)(g_sim + row * 1024))[tid];
    float z0 = v.x * 0.5f, z1 = v.y * 0.5f, z2 = v.z * 0.5f, z3 = v.w * 0.5f;

    float m = fmaxf(fmaxf(z0, z1), fmaxf(z2, z3));
    m = warp_max(m);
    if (lane == 0) sm1[wid] = m;
    __syncthreads();
    m = fmaxf(fmaxf(fmaxf(sm1[0], sm1[1]), fmaxf(sm1[2], sm1[3])),
              fmaxf(fmaxf(sm1[4], sm1[5]), fmaxf(sm1[6], sm1[7])));
    __syncthreads();
    z0 -= m; z1 -= m; z2 -= m; z3 -= m;

    // Newton from tau=-1 (f(-1) >= 0, f convex decreasing -> monotone approach)
    float tau = -1.0f;
#pragma unroll 1
    for (int it = 0; it < 12; it++) {
        float r0 = fmaxf(z0 - tau, 0.f), r1 = fmaxf(z1 - tau, 0.f);
        float r2 = fmaxf(z2 - tau, 0.f), r3 = fmaxf(z3 - tau, 0.f);
        float s1 = (r0 + r1) + (r2 + r3);
        float s2 = (r0 * r0 + r1 * r1) + (r2 * r2 + r3 * r3);
        s1 = warp_sum(s1);
        s2 = warp_sum(s2);
        if (lane == 0) { sm1[wid] = s1; sm2[wid] = s2; }
        __syncthreads();
        float S1 = ((sm1[0] + sm1[1]) + (sm1[2] + sm1[3])) +
                   ((sm1[4] + sm1[5]) + (sm1[6] + sm1[7]));
        float S2 = ((sm2[0] + sm2[1]) + (sm2[2] + sm2[3])) +
                   ((sm2[4] + sm2[5]) + (sm2[6] + sm2[7]));
        __syncthreads();
        tau += (S2 - 1.0f) / (2.0f * S1);
    }
    float a0 = fmaxf(z0 - tau, 0.f), a1 = fmaxf(z1 - tau, 0.f);
    float a2 = fmaxf(z2 - tau, 0.f), a3 = fmaxf(z3 - tau, 0.f);
    a0 *= a0; a1 *= a1; a2 *= a2; a3 *= a3;
    __nv_bfloat16 l0, l1, l2, l3;
    uint32_t h01 = packsplit(a0, a1, l0, l1);
    uint32_t h23 = packsplit(a2, a3, l2, l3);
    size_t base = row * 1024 + (size_t)tid * 4;
    *(uint2*)(ab_hi + base) = make_uint2(h01, h23);
    *(uint2*)(ab_lo + base) = make_uint2(pack2(l0, l1), pack2(l2, l3));
}

// ---------------------------------------------------------------------------
// out = attn @ V per bh.  CTA 128(i) x 64(d), 2-stage pipeline, K=1024/64
// ---------------------------------------------------------------------------
#define AV_STAGE_E (2 * TILE_E + 2 * BTILE_E)
#define AV_SMEM (2 * AV_STAGE_E * 2)   // 110592 B

__device__ __forceinline__ void av_load_chunk(__nv_bfloat16* st,
                                              const __nv_bfloat16* aH, const __nv_bfloat16* aL,
                                              const __nv_bfloat16* bH, const __nv_bfloat16* bL,
                                              int tid) {
    tile_async(st, aH, 128, 1024, tid);
    tile_async(st + TILE_E, aL, 128, 1024, tid);
    tile_async(st + 2 * TILE_E, bH, 64, 1024, tid);
    tile_async(st + 2 * TILE_E + BTILE_E, bL, 64, 1024, tid);
}

__global__ void __launch_bounds__(256, 2) av_mma() {
    extern __shared__ __nv_bfloat16 smp[];
    const int tid = threadIdx.x, wid = tid >> 5, lane = tid & 31;
    const int g = lane >> 2, q = lane & 3;
    const int i0 = blockIdx.x * 128, bh = blockIdx.y;
    const int wm0 = (wid >> 1) * 32, wn0 = (wid & 1) * 32;

    const __nv_bfloat16* gah = ab_hi + ((size_t)(bh << 10) + i0) * 1024;
    const __nv_bfloat16* gal = ab_lo + ((size_t)(bh << 10) + i0) * 1024;
    const __nv_bfloat16* gbh = vbT_hi + (size_t)bh * 64 * 1024;
    const __nv_bfloat16* gbl = vbT_lo + (size_t)bh * 64 * 1024;

    av_load_chunk(smp, gah, gal, gbh, gbl, tid);
    CP_COMMIT();

    float c[2][4][4] = {};
    for (int ch = 0; ch < 16; ch++) {
        if (ch + 1 < 16) {
            __nv_bfloat16* nst = smp + ((ch + 1) & 1) * AV_STAGE_E;
            av_load_chunk(nst, gah + (ch + 1) * 64, gal + (ch + 1) * 64,
                          gbh + (ch + 1) * 64, gbl + (ch + 1) * 64, tid);
            CP_COMMIT();
            CP_WAIT1();
        } else {
            CP_WAIT0();
        }
        __syncthreads();
        const __nv_bfloat16* st = smp + (ch & 1) * AV_STAGE_E;
        const __nv_bfloat16 *AH = st, *AL = st + TILE_E,
                            *BHs = st + 2 * TILE_E, *BLs = st + 2 * TILE_E + BTILE_E;
#pragma unroll
        for (int k0 = 0; k0 < 64; k0 += 16) {
            uint32_t aH[2][4], aL[2][4], bH[4][2], bL[4][2];
#pragma unroll
            for (int mf = 0; mf < 2; mf++) {
                ldA(aH[mf], AH, wm0 + mf * 16, k0, g, q);
                ldA(aL[mf], AL, wm0 + mf * 16, k0, g, q);
            }
#pragma unroll
            for (int nf = 0; nf < 4; nf++) {
                ldB(bH[nf], BHs, wn0 + nf * 8, k0, g, q);
                ldB(bL[nf], BLs, wn0 + nf * 8, k0, g, q);
            }
#pragma unroll
            for (int mf = 0; mf < 2; mf++)
#pragma unroll
                for (int nf = 0; nf < 4; nf++) {
                    mma16816(c[mf][nf], aH[mf], bH[nf]);
                    mma16816(c[mf][nf], aH[mf], bL[nf]);
                    mma16816(c[mf][nf], aL[mf], bH[nf]);
                }
        }
        __syncthreads();
    }
    const int b = bh >> 3, h = bh & 7;
#pragma unroll
    for (int mf = 0; mf < 2; mf++)
#pragma unroll
        for (int nf = 0; nf < 4; nf++) {
            int d = wn0 + nf * 8 + q * 2;
#pragma unroll
            for (int half = 0; half < 2; half++) {
                int i = i0 + wm0 + mf * 16 + g + half * 8;
                __nv_bfloat16 l0, l1;
                uint32_t hp = packsplit(c[mf][nf][half * 2],
                                        c[mf][nf][half * 2 + 1], l0, l1);
                size_t base = ((size_t)b * 1024 + i) * 512 + h * 64 + d;
                *(uint32_t*)(ob_hi + base) = hp;
                *(uint32_t*)(ob_lo + base) = pack2(l0, l1);
            }
        }
}

// ---------------------------------------------------------------------------
// final = o @ w_out  (M=4096, N=512, K=512), 2-stage pipeline -> fp32 out
// ---------------------------------------------------------------------------
__global__ void __launch_bounds__(256) out_mma(float* __restrict__ out) {
    extern __shared__ __nv_bfloat16 smp[];
    const int tid = threadIdx.x, wid = tid >> 5, lane = tid & 31;
    const int g = lane >> 2, q = lane & 3;
    const int row0 = blockIdx.y * 128, col0 = blockIdx.x * 128;
    const int wm0 = (wid >> 2) * 64, wn0 = (wid & 3) * 32;

    const __nv_bfloat16* gah = ob_hi + (size_t)row0 * 512;
    const __nv_bfloat16* gal = ob_lo + (size_t)row0 * 512;
    const __nv_bfloat16* gbh = woutT_hi + (size_t)col0 * 512;
    const __nv_bfloat16* gbl = woutT_lo + (size_t)col0 * 512;

    qkv_load_chunk(smp, gah, gal, gbh, gbl, tid);
    CP_COMMIT();

    float c[4][4][4] = {};
    for (int ch = 0; ch < 8; ch++) {
        if (ch + 1 < 8) {
            __nv_bfloat16* nst = smp + ((ch + 1) & 1) * STAGE4_E;
            qkv_load_chunk(nst, gah + (ch + 1) * 64, gal + (ch + 1) * 64,
                           gbh + (ch + 1) * 64, gbl + (ch + 1) * 64, tid);
            CP_COMMIT();
            CP_WAIT1();
        } else {
            CP_WAIT0();
        }
        __syncthreads();
        gemm_compute_128(c, smp + (ch & 1) * STAGE4_E, wm0, wn0, g, q);
        __syncthreads();
    }
#pragma unroll
    for (int mf = 0; mf < 4; mf++)
#pragma unroll
        for (int nf = 0; nf < 4; nf++) {
            int n = col0 + wn0 + nf * 8 + q * 2;
#pragma unroll
            for (int half = 0; half < 2; half++) {
                int m = row0 + wm0 + mf * 16 + g + half * 8;
                *(float2*)(out + (size_t)m * 512 + n) =
                    make_float2(c[mf][nf][half * 2], c[mf][nf][half * 2 + 1]);
            }
        }
}

// ---------------------------------------------------------------------------
// kernel_launch
// ---------------------------------------------------------------------------
extern "C" void kernel_launch(void* const* d_in, const int* in_sizes, int n_in,
                              void* d_out, int out_size) {
    (void)in_sizes; (void)n_in; (void)out_size;
    const float* x     = (const float*)d_in[0];
    const float* w_qkv = (const float*)d_in[1];
    const float* w_out = (const float*)d_in[2];
    float* out = (float*)d_out;

    cudaFuncSetAttribute(qkv_mma, cudaFuncAttributeMaxDynamicSharedMemorySize, QKV_SMEM);
    cudaFuncSetAttribute(sim_mma, cudaFuncAttributeMaxDynamicSharedMemorySize, SIM_SMEM);
    cudaFuncSetAttribute(av_mma,  cudaFuncAttributeMaxDynamicSharedMemorySize, AV_SMEM);
    cudaFuncSetAttribute(out_mma, cudaFuncAttributeMaxDynamicSharedMemorySize, QKV_SMEM);

    __nv_bfloat16 *wqh, *wql, *woh, *wol;
    cudaGetSymbolAddress((void**)&wqh, wqkvT_hi);
    cudaGetSymbolAddress((void**)&wql, wqkvT_lo);
    cudaGetSymbolAddress((void**)&woh, woutT_hi);
    cudaGetSymbolAddress((void**)&wol, woutT_lo);

    conv_x<<<2048, 256>>>(x);
    conv_w<<<3072, 256>>>(w_qkv, wqh, wql, 1536);
    conv_w<<<1024, 256>>>(w_out, woh, wol, 512);
    qkv_mma<<<dim3(12, 32), 256, QKV_SMEM>>>();
    vtrans<<<dim3(32, 2, 32), 256>>>();
    sim_mma<<<dim3(8, 8, 32), 256, SIM_SMEM>>>();
    entmax_k<<<BH_ * N_, 256>>>();
    av_mma<<<dim3(8, 32), 256, AV_SMEM>>>();
    out_mma<<<dim3(4, 32), 256, QKV_SMEM>>>(out);
}

// round 8
// speedup vs baseline: 2.7272x; 1.5869x over previous
#include <cuda_runtime.h>
#include <cuda_bf16.h>
#include <cstdint>

#define B_   4
#define N_   1024
#define DIM_ 512
#define H_   8
#define D_   64
#define BH_  32
#define SCALE_ 0.125f

#define S32  40     // row stride (elems) for K-chunk-32 tiles
#define S64  72     // row stride (elems) for K=64 tiles

// ---------------------------------------------------------------------------
// Global scratch
// ---------------------------------------------------------------------------
__device__ __nv_bfloat16 xb_hi[4096 * 512], xb_lo[4096 * 512];
__device__ __nv_bfloat16 wqkvT_hi[1536 * 512], wqkvT_lo[1536 * 512];
__device__ __nv_bfloat16 woutT_hi[512 * 512], woutT_lo[512 * 512];
__device__ __nv_bfloat16 qb_hi[BH_ * N_ * D_], qb_lo[BH_ * N_ * D_];
__device__ __nv_bfloat16 kb_hi[BH_ * N_ * D_], kb_lo[BH_ * N_ * D_];
__device__ __nv_bfloat16 vb_hi[BH_ * N_ * D_], vb_lo[BH_ * N_ * D_];
__device__ __nv_bfloat16 vbT_hi[BH_ * D_ * N_], vbT_lo[BH_ * D_ * N_];
__device__ float g_sim[(size_t)BH_ * N_ * N_];
__device__ __nv_bfloat16 ab_hi[(size_t)BH_ * N_ * N_], ab_lo[(size_t)BH_ * N_ * N_];
__device__ __nv_bfloat16 ob_hi[4096 * 512], ob_lo[4096 * 512];

// ---------------------------------------------------------------------------
// Helpers
// ---------------------------------------------------------------------------
__device__ __forceinline__ void f32split(float v, __nv_bfloat16& h, __nv_bfloat16& l) {
    h = __float2bfloat16(v);
    l = __float2bfloat16(v - __bfloat162float(h));
}
__device__ __forceinline__ uint32_t pack2(__nv_bfloat16 a, __nv_bfloat16 b) {
    return (uint32_t)__bfloat16_as_ushort(a) |
           ((uint32_t)__bfloat16_as_ushort(b) << 16);
}
__device__ __forceinline__ uint32_t packsplit(float v0, float v1,
                                              __nv_bfloat16& l0, __nv_bfloat16& l1) {
    __nv_bfloat16 h0, h1;
    f32split(v0, h0, l0); f32split(v1, h1, l1);
    return pack2(h0, h1);
}

__device__ __forceinline__ void mma16816(float* c, const uint32_t* a, const uint32_t* b) {
    asm volatile(
        "mma.sync.aligned.m16n8k16.row.col.f32.bf16.bf16.f32 "
        "{%0,%1,%2,%3}, {%4,%5,%6,%7}, {%8,%9}, {%0,%1,%2,%3};"
        : "+f"(c[0]), "+f"(c[1]), "+f"(c[2]), "+f"(c[3])
        : "r"(a[0]), "r"(a[1]), "r"(a[2]), "r"(a[3]), "r"(b[0]), "r"(b[1]));
}

__device__ __forceinline__ uint32_t smaddr(const void* p) {
    uint32_t a;
    asm("{ .reg .u64 t; cvta.to.shared.u64 t, %1; cvt.u32.u64 %0, t; }"
        : "=r"(a) : "l"(p));
    return a;
}
__device__ __forceinline__ void ldsm4(uint32_t* r, uint32_t a) {
    asm volatile("ldmatrix.sync.aligned.m8n8.x4.shared.b16 {%0,%1,%2,%3}, [%4];"
                 : "=r"(r[0]), "=r"(r[1]), "=r"(r[2]), "=r"(r[3]) : "r"(a));
}

__device__ __forceinline__ void cpa16(__nv_bfloat16* dst, const __nv_bfloat16* src) {
    uint32_t s;
    asm("{ .reg .u64 t; cvta.to.shared.u64 t, %1; cvt.u32.u64 %0, t; }"
        : "=r"(s) : "l"(dst));
    asm volatile("cp.async.cg.shared.global [%0], [%1], 16;" :: "r"(s), "l"(src));
}
#define CP_COMMIT() asm volatile("cp.async.commit_group;" ::: "memory")
#define CP_WAIT0()  asm volatile("cp.async.wait_group 0;" ::: "memory")
#define CP_WAIT1()  asm volatile("cp.async.wait_group 1;" ::: "memory")

// async fill of [rows x 32] tile (stride S) — 2 x 16B per row
template<int S>
__device__ __forceinline__ void tile_async32(__nv_bfloat16* dst, const __nv_bfloat16* g,
                                             int rows, int gstride, int tid) {
    for (int i = tid; i < rows * 4; i += 256) {
        int r = i >> 2, q = i & 3;
        cpa16(dst + r * S + q * 8, g + (size_t)r * gstride + q * 8);
    }
}
// async fill of [rows x 64] tile (stride S)
template<int S>
__device__ __forceinline__ void tile_async64(__nv_bfloat16* dst, const __nv_bfloat16* g,
                                             int rows, int gstride, int tid) {
    for (int i = tid; i < rows * 8; i += 256) {
        int r = i >> 3, q = i & 7;
        cpa16(dst + r * S + q * 8, g + (size_t)r * gstride + q * 8);
    }
}

// ---------------------------------------------------------------------------
// Warp GEMM cores (ldmatrix-fed). Tile layout in smem: AH | AL | BH | BL.
// ---------------------------------------------------------------------------
template<int S, int KC>
__device__ __forceinline__ void gemm_tile44(float c[4][4][4], const __nv_bfloat16* st,
                                            int wm0, int wn0, int lane) {
    const int r8 = lane & 7, sel = lane >> 3;
    const uint32_t base = smaddr(st);
    const uint32_t TE = 128 * S * 2;
    const uint32_t aOff = ((wm0 + (sel & 1) * 8 + r8) * S + (sel >> 1) * 8) * 2;
    const uint32_t bOff = ((wn0 + (sel >> 1) * 8 + r8) * S + (sel & 1) * 8) * 2;
    const uint32_t aH0 = base + aOff, aL0 = base + TE + aOff;
    const uint32_t bH0 = base + 2 * TE + bOff, bL0 = base + 3 * TE + bOff;
#pragma unroll
    for (int k0 = 0; k0 < KC; k0 += 16) {
        uint32_t aH[4][4], aL[4][4], bH[4][2], bL[4][2];
#pragma unroll
        for (int mf = 0; mf < 4; mf++) {
            ldsm4(aH[mf], aH0 + mf * (16 * S * 2) + k0 * 2);
            ldsm4(aL[mf], aL0 + mf * (16 * S * 2) + k0 * 2);
        }
#pragma unroll
        for (int p = 0; p < 2; p++) {
            uint32_t t[4];
            ldsm4(t, bH0 + p * (16 * S * 2) + k0 * 2);
            bH[2 * p][0] = t[0]; bH[2 * p][1] = t[1];
            bH[2 * p + 1][0] = t[2]; bH[2 * p + 1][1] = t[3];
            ldsm4(t, bL0 + p * (16 * S * 2) + k0 * 2);
            bL[2 * p][0] = t[0]; bL[2 * p][1] = t[1];
            bL[2 * p + 1][0] = t[2]; bL[2 * p + 1][1] = t[3];
        }
#pragma unroll
        for (int mf = 0; mf < 4; mf++)
#pragma unroll
            for (int nf = 0; nf < 4; nf++) {
                mma16816(c[mf][nf], aH[mf], bH[nf]);
                mma16816(c[mf][nf], aH[mf], bL[nf]);
                mma16816(c[mf][nf], aL[mf], bH[nf]);
            }
    }
}

// 2 m-frags x 4 n-frags variant; A tiles 128 rows, B tiles 64 rows
template<int S, int KC>
__device__ __forceinline__ void gemm_tile24(float c[2][4][4], const __nv_bfloat16* st,
                                            int wm0, int wn0, int lane) {
    const int r8 = lane & 7, sel = lane >> 3;
    const uint32_t base = smaddr(st);
    const uint32_t TA = 128 * S * 2, TB = 64 * S * 2;
    const uint32_t aOff = ((wm0 + (sel & 1) * 8 + r8) * S + (sel >> 1) * 8) * 2;
    const uint32_t bOff = ((wn0 + (sel >> 1) * 8 + r8) * S + (sel & 1) * 8) * 2;
    const uint32_t aH0 = base + aOff, aL0 = base + TA + aOff;
    const uint32_t bH0 = base + 2 * TA + bOff, bL0 = base + 2 * TA + TB + bOff;
#pragma unroll
    for (int k0 = 0; k0 < KC; k0 += 16) {
        uint32_t aH[2][4], aL[2][4], bH[4][2], bL[4][2];
#pragma unroll
        for (int mf = 0; mf < 2; mf++) {
            ldsm4(aH[mf], aH0 + mf * (16 * S * 2) + k0 * 2);
            ldsm4(aL[mf], aL0 + mf * (16 * S * 2) + k0 * 2);
        }
#pragma unroll
        for (int p = 0; p < 2; p++) {
            uint32_t t[4];
            ldsm4(t, bH0 + p * (16 * S * 2) + k0 * 2);
            bH[2 * p][0] = t[0]; bH[2 * p][1] = t[1];
            bH[2 * p + 1][0] = t[2]; bH[2 * p + 1][1] = t[3];
            ldsm4(t, bL0 + p * (16 * S * 2) + k0 * 2);
            bL[2 * p][0] = t[0]; bL[2 * p][1] = t[1];
            bL[2 * p + 1][0] = t[2]; bL[2 * p + 1][1] = t[3];
        }
#pragma unroll
        for (int mf = 0; mf < 2; mf++)
#pragma unroll
            for (int nf = 0; nf < 4; nf++) {
                mma16816(c[mf][nf], aH[mf], bH[nf]);
                mma16816(c[mf][nf], aH[mf], bL[nf]);
                mma16816(c[mf][nf], aL[mf], bH[nf]);
            }
    }
}

// ---------------------------------------------------------------------------
// Conversion prologue
// ---------------------------------------------------------------------------
__global__ void __launch_bounds__(256) conv_x(const float* __restrict__ x) {
    int i = blockIdx.x * 256 + threadIdx.x;
    float4 v = ((const float4*)x)[i];
    __nv_bfloat16 l0, l1, l2, l3;
    uint32_t h01 = packsplit(v.x, v.y, l0, l1);
    uint32_t h23 = packsplit(v.z, v.w, l2, l3);
    *(uint2*)(xb_hi + (size_t)i * 4) = make_uint2(h01, h23);
    *(uint2*)(xb_lo + (size_t)i * 4) = make_uint2(pack2(l0, l1), pack2(l2, l3));
}

__global__ void __launch_bounds__(256) conv_w(const float* __restrict__ w,
                                              __nv_bfloat16* th, __nv_bfloat16* tl,
                                              int cols) {
    int i = blockIdx.x * 256 + threadIdx.x;       // i = n*512 + k
    int n = i >> 9, k = i & 511;
    float v = w[(size_t)k * cols + n];
    __nv_bfloat16 h, l;
    f32split(v, h, l);
    th[i] = h; tl[i] = l;
}

// ---------------------------------------------------------------------------
// qkv = x @ w_qkv  (M=4096, N=1536, K=512): K-chunk 32, 2-stage, 2 CTA/SM
// ---------------------------------------------------------------------------
#define STG32_E (4 * 128 * S32)            // 20480 elems per stage
#define QKV_SMEM (2 * STG32_E * 2)         // 81920 B

__device__ __forceinline__ void load_chunk32(__nv_bfloat16* st,
                                             const __nv_bfloat16* aH, const __nv_bfloat16* aL,
                                             const __nv_bfloat16* bH, const __nv_bfloat16* bL,
                                             int tid) {
    tile_async32<S32>(st + 0 * 128 * S32, aH, 128, 512, tid);
    tile_async32<S32>(st + 1 * 128 * S32, aL, 128, 512, tid);
    tile_async32<S32>(st + 2 * 128 * S32, bH, 128, 512, tid);
    tile_async32<S32>(st + 3 * 128 * S32, bL, 128, 512, tid);
}

__global__ void __launch_bounds__(256, 2) qkv_mma() {
    extern __shared__ __nv_bfloat16 smp[];
    const int tid = threadIdx.x, wid = tid >> 5, lane = tid & 31;
    const int row0 = blockIdx.y * 128, col0 = blockIdx.x * 128;
    const int wm0 = (wid >> 2) * 64, wn0 = (wid & 3) * 32;

    const __nv_bfloat16* gah = xb_hi + (size_t)row0 * 512;
    const __nv_bfloat16* gal = xb_lo + (size_t)row0 * 512;
    const __nv_bfloat16* gbh = wqkvT_hi + (size_t)col0 * 512;
    const __nv_bfloat16* gbl = wqkvT_lo + (size_t)col0 * 512;

    load_chunk32(smp, gah, gal, gbh, gbl, tid);
    CP_COMMIT();

    float c[4][4][4] = {};
    for (int ch = 0; ch < 16; ch++) {
        if (ch + 1 < 16) {
            load_chunk32(smp + ((ch + 1) & 1) * STG32_E,
                         gah + (ch + 1) * 32, gal + (ch + 1) * 32,
                         gbh + (ch + 1) * 32, gbl + (ch + 1) * 32, tid);
            CP_COMMIT();
            CP_WAIT1();
        } else {
            CP_WAIT0();
        }
        __syncthreads();
        gemm_tile44<S32, 32>(c, smp + (ch & 1) * STG32_E, wm0, wn0, lane);
        __syncthreads();
    }

    const int part = col0 >> 9;
    const int q = lane & 3, g = lane >> 2;
    __nv_bfloat16* dh = part == 0 ? qb_hi : part == 1 ? kb_hi : vb_hi;
    __nv_bfloat16* dl = part == 0 ? qb_lo : part == 1 ? kb_lo : vb_lo;
    const float sc = part == 0 ? SCALE_ : 1.0f;
#pragma unroll
    for (int mf = 0; mf < 4; mf++)
#pragma unroll
        for (int nf = 0; nf < 4; nf++) {
            int ncol = (col0 & 511) + wn0 + nf * 8 + q * 2;
            int head = ncol >> 6, d = ncol & 63;
#pragma unroll
            for (int half = 0; half < 2; half++) {
                int m = row0 + wm0 + mf * 16 + g + half * 8;
                __nv_bfloat16 l0, l1;
                uint32_t hp = packsplit(c[mf][nf][half * 2] * sc,
                                        c[mf][nf][half * 2 + 1] * sc, l0, l1);
                size_t base = ((size_t)((m >> 10) * 8 + head) * 1024 + (m & 1023)) * 64 + d;
                *(uint32_t*)(dh + base) = hp;
                *(uint32_t*)(dl + base) = pack2(l0, l1);
            }
        }
}

// ---------------------------------------------------------------------------
// V transpose
// ---------------------------------------------------------------------------
__global__ void __launch_bounds__(256) vtrans() {
    __shared__ __nv_bfloat16 th[32][33], tl[32][33];
    const int bh = blockIdx.z, j0 = blockIdx.x * 32, d0 = blockIdx.y * 32;
    const int tx = threadIdx.x & 31, ty = threadIdx.x >> 5;
    const size_t src = ((size_t)bh * 1024 + j0) * 64 + d0;
    for (int r = ty; r < 32; r += 8) {
        th[r][tx] = vb_hi[src + (size_t)r * 64 + tx];
        tl[r][tx] = vb_lo[src + (size_t)r * 64 + tx];
    }
    __syncthreads();
    const size_t dst = ((size_t)bh * 64 + d0) * 1024 + j0;
    for (int r = ty; r < 32; r += 8) {
        vbT_hi[dst + (size_t)r * 1024 + tx] = th[tx][r];
        vbT_lo[dst + (size_t)r * 1024 + tx] = tl[tx][r];
    }
}

// ---------------------------------------------------------------------------
// sim = Q @ K^T per bh.  CTA 128x128, K=64 single chunk, 2 CTA/SM
// ---------------------------------------------------------------------------
#define SIM_SMEM (4 * 128 * S64 * 2)       // 73728 B

__global__ void __launch_bounds__(256, 2) sim_mma() {
    extern __shared__ __nv_bfloat16 smp[];
    const int tid = threadIdx.x, wid = tid >> 5, lane = tid & 31;
    const int q = lane & 3, g = lane >> 2;
    const int j0 = blockIdx.x * 128, i0 = blockIdx.y * 128, bh = blockIdx.z;
    const int wm0 = (wid >> 2) * 64, wn0 = (wid & 3) * 32;

    tile_async64<S64>(smp + 0 * 128 * S64, qb_hi + ((size_t)(bh << 10) + i0) * 64, 128, 64, tid);
    tile_async64<S64>(smp + 1 * 128 * S64, qb_lo + ((size_t)(bh << 10) + i0) * 64, 128, 64, tid);
    tile_async64<S64>(smp + 2 * 128 * S64, kb_hi + ((size_t)(bh << 10) + j0) * 64, 128, 64, tid);
    tile_async64<S64>(smp + 3 * 128 * S64, kb_lo + ((size_t)(bh << 10) + j0) * 64, 128, 64, tid);
    CP_COMMIT();
    CP_WAIT0();
    __syncthreads();

    float c[4][4][4] = {};
    gemm_tile44<S64, 64>(c, smp, wm0, wn0, lane);

#pragma unroll
    for (int mf = 0; mf < 4; mf++)
#pragma unroll
        for (int nf = 0; nf < 4; nf++) {
            int j = j0 + wn0 + nf * 8 + q * 2;
#pragma unroll
            for (int half = 0; half < 2; half++) {
                int i = i0 + wm0 + mf * 16 + g + half * 8;
                *(float2*)(g_sim + ((size_t)(bh << 10) + i) * 1024 + j) =
                    make_float2(c[mf][nf][half * 2], c[mf][nf][half * 2 + 1]);
            }
        }
}

// ---------------------------------------------------------------------------
// entmax-1.5: warp per row, 32 elems/thread in regs, Newton, no block syncs
// ---------------------------------------------------------------------------
__device__ __forceinline__ float warp_max(float v) {
#pragma unroll
    for (int o = 16; o; o >>= 1) v = fmaxf(v, __shfl_xor_sync(0xffffffffu, v, o));
    return v;
}
__device__ __forceinline__ float warp_sum(float v) {
#pragma unroll
    for (int o = 16; o; o >>= 1) v += __shfl_xor_sync(0xffffffffu, v, o);
    return v;
}

__global__ void __launch_bounds__(256) entmax_k() {
    const int lane = threadIdx.x & 31, wid = threadIdx.x >> 5;
    const size_t row = (size_t)blockIdx.x * 8 + wid;
    const float* p = g_sim + row * 1024;

    float z[32];
    float m = -1e30f;
#pragma unroll
    for (int j = 0; j < 8; j++) {
        float4 v = ((const float4*)p)[j * 32 + lane];
        z[j * 4 + 0] = v.x * 0.5f; z[j * 4 + 1] = v.y * 0.5f;
        z[j * 4 + 2] = v.z * 0.5f; z[j * 4 + 3] = v.w * 0.5f;
        m = fmaxf(m, fmaxf(fmaxf(z[j * 4], z[j * 4 + 1]),
                           fmaxf(z[j * 4 + 2], z[j * 4 + 3])));
    }
    m = warp_max(m);
#pragma unroll
    for (int i = 0; i < 32; i++) z[i] -= m;

    float tau = -1.0f;
#pragma unroll 1
    for (int it = 0; it < 12; it++) {
        float s1 = 0.f, s2 = 0.f;
#pragma unroll
        for (int i = 0; i < 32; i++) {
            float r = z[i] - tau;
            if (r > 0.f) { s1 += r; s2 = fmaf(r, r, s2); }
        }
        s1 = warp_sum(s1);
        s2 = warp_sum(s2);
        tau += (s2 - 1.0f) / fmaxf(2.0f * s1, 1e-20f);
    }
#pragma unroll
    for (int j = 0; j < 8; j++) {
        float a0 = fmaxf(z[j * 4 + 0] - tau, 0.f), a1 = fmaxf(z[j * 4 + 1] - tau, 0.f);
        float a2 = fmaxf(z[j * 4 + 2] - tau, 0.f), a3 = fmaxf(z[j * 4 + 3] - tau, 0.f);
        a0 *= a0; a1 *= a1; a2 *= a2; a3 *= a3;
        __nv_bfloat16 l0, l1, l2, l3;
        uint32_t h01 = packsplit(a0, a1, l0, l1);
        uint32_t h23 = packsplit(a2, a3, l2, l3);
        size_t base = row * 1024 + (size_t)(j * 32 + lane) * 4;
        *(uint2*)(ab_hi + base) = make_uint2(h01, h23);
        *(uint2*)(ab_lo + base) = make_uint2(pack2(l0, l1), pack2(l2, l3));
    }
}

// ---------------------------------------------------------------------------
// out = attn @ V per bh.  CTA 128x64, K-chunk 32, 2-stage, 2 CTA/SM
// ---------------------------------------------------------------------------
#define AVSTG_E (2 * 128 * S32 + 2 * 64 * S32)   // 15360 elems
#define AV_SMEM (2 * AVSTG_E * 2)                // 61440 B

__device__ __forceinline__ void av_load32(__nv_bfloat16* st,
                                          const __nv_bfloat16* aH, const __nv_bfloat16* aL,
                                          const __nv_bfloat16* bH, const __nv_bfloat16* bL,
                                          int tid) {
    tile_async32<S32>(st, aH, 128, 1024, tid);
    tile_async32<S32>(st + 128 * S32, aL, 128, 1024, tid);
    tile_async32<S32>(st + 2 * 128 * S32, bH, 64, 1024, tid);
    tile_async32<S32>(st + 2 * 128 * S32 + 64 * S32, bL, 64, 1024, tid);
}

__global__ void __launch_bounds__(256, 2) av_mma() {
    extern __shared__ __nv_bfloat16 smp[];
    const int tid = threadIdx.x, wid = tid >> 5, lane = tid & 31;
    const int q = lane & 3, g = lane >> 2;
    const int i0 = blockIdx.x * 128, bh = blockIdx.y;
    const int wm0 = (wid >> 1) * 32, wn0 = (wid & 1) * 32;

    const __nv_bfloat16* gah = ab_hi + ((size_t)(bh << 10) + i0) * 1024;
    const __nv_bfloat16* gal = ab_lo + ((size_t)(bh << 10) + i0) * 1024;
    const __nv_bfloat16* gbh = vbT_hi + (size_t)bh * 64 * 1024;
    const __nv_bfloat16* gbl = vbT_lo + (size_t)bh * 64 * 1024;

    av_load32(smp, gah, gal, gbh, gbl, tid);
    CP_COMMIT();

    float c[2][4][4] = {};
    for (int ch = 0; ch < 32; ch++) {
        if (ch + 1 < 32) {
            av_load32(smp + ((ch + 1) & 1) * AVSTG_E,
                      gah + (ch + 1) * 32, gal + (ch + 1) * 32,
                      gbh + (ch + 1) * 32, gbl + (ch + 1) * 32, tid);
            CP_COMMIT();
            CP_WAIT1();
        } else {
            CP_WAIT0();
        }
        __syncthreads();
        gemm_tile24<S32, 32>(c, smp + (ch & 1) * AVSTG_E, wm0, wn0, lane);
        __syncthreads();
    }
    const int b = bh >> 3, h = bh & 7;
#pragma unroll
    for (int mf = 0; mf < 2; mf++)
#pragma unroll
        for (int nf = 0; nf < 4; nf++) {
            int d = wn0 + nf * 8 + q * 2;
#pragma unroll
            for (int half = 0; half < 2; half++) {
                int i = i0 + wm0 + mf * 16 + g + half * 8;
                __nv_bfloat16 l0, l1;
                uint32_t hp = packsplit(c[mf][nf][half * 2],
                                        c[mf][nf][half * 2 + 1], l0, l1);
                size_t base = ((size_t)b * 1024 + i) * 512 + h * 64 + d;
                *(uint32_t*)(ob_hi + base) = hp;
                *(uint32_t*)(ob_lo + base) = pack2(l0, l1);
            }
        }
}

// ---------------------------------------------------------------------------
// final = o @ w_out  (M=4096, N=512, K=512), K-chunk 32, 2-stage -> fp32 out
// ---------------------------------------------------------------------------
__global__ void __launch_bounds__(256, 2) out_mma(float* __restrict__ out) {
    extern __shared__ __nv_bfloat16 smp[];
    const int tid = threadIdx.x, wid = tid >> 5, lane = tid & 31;
    const int q = lane & 3, g = lane >> 2;
    const int row0 = blockIdx.y * 128, col0 = blockIdx.x * 128;
    const int wm0 = (wid >> 2) * 64, wn0 = (wid & 3) * 32;

    const __nv_bfloat16* gah = ob_hi + (size_t)row0 * 512;
    const __nv_bfloat16* gal = ob_lo + (size_t)row0 * 512;
    const __nv_bfloat16* gbh = woutT_hi + (size_t)col0 * 512;
    const __nv_bfloat16* gbl = woutT_lo + (size_t)col0 * 512;

    load_chunk32(smp, gah, gal, gbh, gbl, tid);
    CP_COMMIT();

    float c[4][4][4] = {};
    for (int ch = 0; ch < 16; ch++) {
        if (ch + 1 < 16) {
            load_chunk32(smp + ((ch + 1) & 1) * STG32_E,
                         gah + (ch + 1) * 32, gal + (ch + 1) * 32,
                         gbh + (ch + 1) * 32, gbl + (ch + 1) * 32, tid);
            CP_COMMIT();
            CP_WAIT1();
        } else {
            CP_WAIT0();
        }
        __syncthreads();
        gemm_tile44<S32, 32>(c, smp + (ch & 1) * STG32_E, wm0, wn0, lane);
        __syncthreads();
    }
#pragma unroll
    for (int mf = 0; mf < 4; mf++)
#pragma unroll
        for (int nf = 0; nf < 4; nf++) {
            int n = col0 + wn0 + nf * 8 + q * 2;
#pragma unroll
            for (int half = 0; half < 2; half++) {
                int m = row0 + wm0 + mf * 16 + g + half * 8;
                *(float2*)(out + (size_t)m * 512 + n) =
                    make_float2(c[mf][nf][half * 2], c[mf][nf][half * 2 + 1]);
            }
        }
}

// ---------------------------------------------------------------------------
// kernel_launch
// ---------------------------------------------------------------------------
extern "C" void kernel_launch(void* const* d_in, const int* in_sizes, int n_in,
                              void* d_out, int out_size) {
    (void)in_sizes; (void)n_in; (void)out_size;
    const float* x     = (const float*)d_in[0];
    const float* w_qkv = (const float*)d_in[1];
    const float* w_out = (const float*)d_in[2];
    float* out = (float*)d_out;

    cudaFuncSetAttribute(qkv_mma, cudaFuncAttributeMaxDynamicSharedMemorySize, QKV_SMEM);
    cudaFuncSetAttribute(sim_mma, cudaFuncAttributeMaxDynamicSharedMemorySize, SIM_SMEM);
    cudaFuncSetAttribute(av_mma,  cudaFuncAttributeMaxDynamicSharedMemorySize, AV_SMEM);
    cudaFuncSetAttribute(out_mma, cudaFuncAttributeMaxDynamicSharedMemorySize, QKV_SMEM);

    __nv_bfloat16 *wqh, *wql, *woh, *wol;
    cudaGetSymbolAddress((void**)&wqh, wqkvT_hi);
    cudaGetSymbolAddress((void**)&wql, wqkvT_lo);
    cudaGetSymbolAddress((void**)&woh, woutT_hi);
    cudaGetSymbolAddress((void**)&wol, woutT_lo);

    conv_x<<<2048, 256>>>(x);
    conv_w<<<3072, 256>>>(w_qkv, wqh, wql, 1536);
    conv_w<<<1024, 256>>>(w_out, woh, wol, 512);
    qkv_mma<<<dim3(12, 32), 256, QKV_SMEM>>>();
    vtrans<<<dim3(32, 2, 32), 256>>>();
    sim_mma<<<dim3(8, 8, 32), 256, SIM_SMEM>>>();
    entmax_k<<<4096, 256>>>();
    av_mma<<<dim3(8, 32), 256, AV_SMEM>>>();
    out_mma<<<dim3(4, 32), 256, QKV_SMEM>>>(out);
}

// round 10
// speedup vs baseline: 2.7613x; 1.0125x over previous
#include <cuda_runtime.h>
#include <cuda_bf16.h>
#include <cstdint>

#define B_   4
#define N_   1024
#define DIM_ 512
#define H_   8
#define D_   64
#define BH_  32
#define SCALE_ 0.125f

#define S32  40     // smem row stride (elems) for K-chunk-32 tiles
#define S64  72     // smem row stride (elems) for K=64 tiles

// ---------------------------------------------------------------------------
// Global scratch
// ---------------------------------------------------------------------------
__device__ __nv_bfloat16 xb_hi[4096 * 512], xb_lo[4096 * 512];
__device__ __nv_bfloat16 wqkvT_hi[1536 * 512], wqkvT_lo[1536 * 512];
__device__ __nv_bfloat16 woutT_hi[512 * 512], woutT_lo[512 * 512];
__device__ __nv_bfloat16 qb_hi[BH_ * N_ * D_], qb_lo[BH_ * N_ * D_];
__device__ __nv_bfloat16 kb_hi[BH_ * N_ * D_], kb_lo[BH_ * N_ * D_];
__device__ __nv_bfloat16 vb_hi[BH_ * N_ * D_], vb_lo[BH_ * N_ * D_];
__device__ __nv_bfloat16 vbT_hi[BH_ * D_ * N_], vbT_lo[BH_ * D_ * N_];
__device__ float g_sim[(size_t)BH_ * N_ * N_];
__device__ __nv_bfloat16 ab_hi[(size_t)BH_ * N_ * N_], ab_lo[(size_t)BH_ * N_ * N_];
__device__ __nv_bfloat16 ob_hi[4096 * 512], ob_lo[4096 * 512];

// ---------------------------------------------------------------------------
// Helpers
// ---------------------------------------------------------------------------
__device__ __forceinline__ void f32split(float v, __nv_bfloat16& h, __nv_bfloat16& l) {
    h = __float2bfloat16(v);
    l = __float2bfloat16(v - __bfloat162float(h));
}
__device__ __forceinline__ uint32_t pack2(__nv_bfloat16 a, __nv_bfloat16 b) {
    return (uint32_t)__bfloat16_as_ushort(a) |
           ((uint32_t)__bfloat16_as_ushort(b) << 16);
}
__device__ __forceinline__ uint32_t packsplit(float v0, float v1,
                                              __nv_bfloat16& l0, __nv_bfloat16& l1) {
    __nv_bfloat16 h0, h1;
    f32split(v0, h0, l0); f32split(v1, h1, l1);
    return pack2(h0, h1);
}

__device__ __forceinline__ void mma16816(float* c, const uint32_t* a, const uint32_t* b) {
    asm volatile(
        "mma.sync.aligned.m16n8k16.row.col.f32.bf16.bf16.f32 "
        "{%0,%1,%2,%3}, {%4,%5,%6,%7}, {%8,%9}, {%0,%1,%2,%3};"
        : "+f"(c[0]), "+f"(c[1]), "+f"(c[2]), "+f"(c[3])
        : "r"(a[0]), "r"(a[1]), "r"(a[2]), "r"(a[3]), "r"(b[0]), "r"(b[1]));
}

__device__ __forceinline__ uint32_t smaddr(const void* p) {
    uint32_t a;
    asm("{ .reg .u64 t; cvta.to.shared.u64 t, %1; cvt.u32.u64 %0, t; }"
        : "=r"(a) : "l"(p));
    return a;
}
__device__ __forceinline__ void ldsm4(uint32_t* r, uint32_t a) {
    asm volatile("ldmatrix.sync.aligned.m8n8.x4.shared.b16 {%0,%1,%2,%3}, [%4];"
                 : "=r"(r[0]), "=r"(r[1]), "=r"(r[2]), "=r"(r[3]) : "r"(a));
}

__device__ __forceinline__ void cpa16(__nv_bfloat16* dst, const __nv_bfloat16* src) {
    uint32_t s;
    asm("{ .reg .u64 t; cvta.to.shared.u64 t, %1; cvt.u32.u64 %0, t; }"
        : "=r"(s) : "l"(dst));
    asm volatile("cp.async.cg.shared.global [%0], [%1], 16;" :: "r"(s), "l"(src));
}
#define CP_COMMIT() asm volatile("cp.async.commit_group;" ::: "memory")
#define CP_WAIT0()  asm volatile("cp.async.wait_group 0;" ::: "memory")
#define CP_WAIT1()  asm volatile("cp.async.wait_group 1;" ::: "memory")

// async fill of [rows x 32] tile (stride S)
template<int S>
__device__ __forceinline__ void tile_async32(__nv_bfloat16* dst, const __nv_bfloat16* g,
                                             int rows, int gstride, int tid) {
    for (int i = tid; i < rows * 4; i += 256) {
        int r = i >> 2, q = i & 3;
        cpa16(dst + r * S + q * 8, g + (size_t)r * gstride + q * 8);
    }
}
// async fill of [rows x 64] tile (stride S)
template<int S>
__device__ __forceinline__ void tile_async64(__nv_bfloat16* dst, const __nv_bfloat16* g,
                                             int rows, int gstride, int tid) {
    for (int i = tid; i < rows * 8; i += 256) {
        int r = i >> 3, q = i & 7;
        cpa16(dst + r * S + q * 8, g + (size_t)r * gstride + q * 8);
    }
}

// ---------------------------------------------------------------------------
// Warp GEMM cores (ldmatrix-fed). Tile layout: AH[128xS] AL[128xS] BH[64xS] BL[64xS]
// ---------------------------------------------------------------------------
template<int S, int KC>
__device__ __forceinline__ void gemm_tile24(float c[2][4][4], const __nv_bfloat16* st,
                                            int wm0, int wn0, int lane) {
    const int r8 = lane & 7, sel = lane >> 3;
    const uint32_t base = smaddr(st);
    const uint32_t TA = 128 * S * 2, TB = 64 * S * 2;
    const uint32_t aOff = ((wm0 + (sel & 1) * 8 + r8) * S + (sel >> 1) * 8) * 2;
    const uint32_t bOff = ((wn0 + (sel >> 1) * 8 + r8) * S + (sel & 1) * 8) * 2;
    const uint32_t aH0 = base + aOff, aL0 = base + TA + aOff;
    const uint32_t bH0 = base + 2 * TA + bOff, bL0 = base + 2 * TA + TB + bOff;
#pragma unroll
    for (int k0 = 0; k0 < KC; k0 += 16) {
        uint32_t aH[2][4], aL[2][4], bH[4][2], bL[4][2];
#pragma unroll
        for (int mf = 0; mf < 2; mf++) {
            ldsm4(aH[mf], aH0 + mf * (16 * S * 2) + k0 * 2);
            ldsm4(aL[mf], aL0 + mf * (16 * S * 2) + k0 * 2);
        }
#pragma unroll
        for (int p = 0; p < 2; p++) {
            uint32_t t[4];
            ldsm4(t, bH0 + p * (16 * S * 2) + k0 * 2);
            bH[2 * p][0] = t[0]; bH[2 * p][1] = t[1];
            bH[2 * p + 1][0] = t[2]; bH[2 * p + 1][1] = t[3];
            ldsm4(t, bL0 + p * (16 * S * 2) + k0 * 2);
            bL[2 * p][0] = t[0]; bL[2 * p][1] = t[1];
            bL[2 * p + 1][0] = t[2]; bL[2 * p + 1][1] = t[3];
        }
#pragma unroll
        for (int mf = 0; mf < 2; mf++)
#pragma unroll
            for (int nf = 0; nf < 4; nf++) {
                mma16816(c[mf][nf], aH[mf], bH[nf]);
                mma16816(c[mf][nf], aH[mf], bL[nf]);
                mma16816(c[mf][nf], aL[mf], bH[nf]);
            }
    }
}

// 4x4 core for sim (A,B both 128 rows)
template<int S, int KC>
__device__ __forceinline__ void gemm_tile44(float c[4][4][4], const __nv_bfloat16* st,
                                            int wm0, int wn0, int lane) {
    const int r8 = lane & 7, sel = lane >> 3;
    const uint32_t base = smaddr(st);
    const uint32_t TE = 128 * S * 2;
    const uint32_t aOff = ((wm0 + (sel & 1) * 8 + r8) * S + (sel >> 1) * 8) * 2;
    const uint32_t bOff = ((wn0 + (sel >> 1) * 8 + r8) * S + (sel & 1) * 8) * 2;
    const uint32_t aH0 = base + aOff, aL0 = base + TE + aOff;
    const uint32_t bH0 = base + 2 * TE + bOff, bL0 = base + 3 * TE + bOff;
#pragma unroll
    for (int k0 = 0; k0 < KC; k0 += 16) {
        uint32_t aH[4][4], aL[4][4], bH[4][2], bL[4][2];
#pragma unroll
        for (int mf = 0; mf < 4; mf++) {
            ldsm4(aH[mf], aH0 + mf * (16 * S * 2) + k0 * 2);
            ldsm4(aL[mf], aL0 + mf * (16 * S * 2) + k0 * 2);
        }
#pragma unroll
        for (int p = 0; p < 2; p++) {
            uint32_t t[4];
            ldsm4(t, bH0 + p * (16 * S * 2) + k0 * 2);
            bH[2 * p][0] = t[0]; bH[2 * p][1] = t[1];
            bH[2 * p + 1][0] = t[2]; bH[2 * p + 1][1] = t[3];
            ldsm4(t, bL0 + p * (16 * S * 2) + k0 * 2);
            bL[2 * p][0] = t[0]; bL[2 * p][1] = t[1];
            bL[2 * p + 1][0] = t[2]; bL[2 * p + 1][1] = t[3];
        }
#pragma unroll
        for (int mf = 0; mf < 4; mf++)
#pragma unroll
            for (int nf = 0; nf < 4; nf++) {
                mma16816(c[mf][nf], aH[mf], bH[nf]);
                mma16816(c[mf][nf], aH[mf], bL[nf]);
                mma16816(c[mf][nf], aL[mf], bH[nf]);
            }
    }
}

// ---------------------------------------------------------------------------
// Conversion prologue
// ---------------------------------------------------------------------------
__global__ void __launch_bounds__(256) conv_x(const float* __restrict__ x) {
    int i = blockIdx.x * 256 + threadIdx.x;
    float4 v = ((const float4*)x)[i];
    __nv_bfloat16 l0, l1, l2, l3;
    uint32_t h01 = packsplit(v.x, v.y, l0, l1);
    uint32_t h23 = packsplit(v.z, v.w, l2, l3);
    *(uint2*)(xb_hi + (size_t)i * 4) = make_uint2(h01, h23);
    *(uint2*)(xb_lo + (size_t)i * 4) = make_uint2(pack2(l0, l1), pack2(l2, l3));
}

__global__ void __launch_bounds__(256) conv_w(const float* __restrict__ w,
                                              __nv_bfloat16* th, __nv_bfloat16* tl,
                                              int cols) {
    int i = blockIdx.x * 256 + threadIdx.x;       // i = n*512 + k
    int n = i >> 9, k = i & 511;
    float v = w[(size_t)k * cols + n];
    __nv_bfloat16 h, l;
    f32split(v, h, l);
    th[i] = h; tl[i] = l;
}

// ---------------------------------------------------------------------------
// Shared 3-stage pipelined GEMM body: C[128 x 64] tile, K chunks of 32.
// Layout per stage: AH[128xS32] AL[128xS32] BH[64xS32] BL[64xS32]
// ---------------------------------------------------------------------------
#define STG_E ((2 * 128 + 2 * 64) * S32)    // 15360 elems = 30720 B
#define PIPE_SMEM (3 * STG_E * 2)           // 92160 B

__device__ __forceinline__ void pipe_load(__nv_bfloat16* st,
                                          const __nv_bfloat16* aH, const __nv_bfloat16* aL,
                                          const __nv_bfloat16* bH, const __nv_bfloat16* bL,
                                          int astride, int tid) {
    tile_async32<S32>(st, aH, 128, astride, tid);
    tile_async32<S32>(st + 128 * S32, aL, 128, astride, tid);
    tile_async32<S32>(st + 2 * 128 * S32, bH, 64, astride, tid);
    tile_async32<S32>(st + 2 * 128 * S32 + 64 * S32, bL, 64, astride, tid);
}

template<int NC>
__device__ __forceinline__ void pipe_gemm(float c[2][4][4], __nv_bfloat16* smp,
                                          const __nv_bfloat16* gah, const __nv_bfloat16* gal,
                                          const __nv_bfloat16* gbh, const __nv_bfloat16* gbl,
                                          int astride, int tid, int wm0, int wn0, int lane) {
    pipe_load(smp, gah, gal, gbh, gbl, astride, tid);
    CP_COMMIT();
    pipe_load(smp + STG_E, gah + 32, gal + 32, gbh + 32, gbl + 32, astride, tid);
    CP_COMMIT();
#pragma unroll 1
    for (int ch = 0; ch < NC; ch++) {
        CP_WAIT1();
        __syncthreads();
        if (ch + 2 < NC) {
            int nx = (ch + 2) % 3;
            pipe_load(smp + nx * STG_E, gah + (ch + 2) * 32, gal + (ch + 2) * 32,
                      gbh + (ch + 2) * 32, gbl + (ch + 2) * 32, astride, tid);
        }
        CP_COMMIT();
        gemm_tile24<S32, 32>(c, smp + (ch % 3) * STG_E, wm0, wn0, lane);
    }
}

// ---------------------------------------------------------------------------
// qkv = x @ w_qkv  (M=4096, N=1536, K=512): tile 128x64, grid 768
// ---------------------------------------------------------------------------
__global__ void __launch_bounds__(256, 2) qkv_mma() {
    extern __shared__ __nv_bfloat16 smp[];
    const int tid = threadIdx.x, wid = tid >> 5, lane = tid & 31;
    const int q = lane & 3, g = lane >> 2;
    const int row0 = blockIdx.y * 128, col0 = blockIdx.x * 64;
    const int wm0 = (wid & 3) * 32, wn0 = (wid >> 2) * 32;

    float c[2][4][4] = {};
    pipe_gemm<16>(c, smp,
                  xb_hi + (size_t)row0 * 512, xb_lo + (size_t)row0 * 512,
                  wqkvT_hi + (size_t)col0 * 512, wqkvT_lo + (size_t)col0 * 512,
                  512, tid, wm0, wn0, lane);

    const int part = col0 >> 9;
    const int head = (col0 >> 6) & 7;
    __nv_bfloat16* dh = part == 0 ? qb_hi : part == 1 ? kb_hi : vb_hi;
    __nv_bfloat16* dl = part == 0 ? qb_lo : part == 1 ? kb_lo : vb_lo;
    const float sc = part == 0 ? SCALE_ : 1.0f;
#pragma unroll
    for (int mf = 0; mf < 2; mf++)
#pragma unroll
        for (int nf = 0; nf < 4; nf++) {
            int d = wn0 + nf * 8 + q * 2;
#pragma unroll
            for (int half = 0; half < 2; half++) {
                int m = row0 + wm0 + mf * 16 + g + half * 8;
                __nv_bfloat16 l0, l1;
                uint32_t hp = packsplit(c[mf][nf][half * 2] * sc,
                                        c[mf][nf][half * 2 + 1] * sc, l0, l1);
                size_t base = ((size_t)((m >> 10) * 8 + head) * 1024 + (m & 1023)) * 64 + d;
                *(uint32_t*)(dh + base) = hp;
                *(uint32_t*)(dl + base) = pack2(l0, l1);
            }
        }
}

// ---------------------------------------------------------------------------
// V transpose
// ---------------------------------------------------------------------------
__global__ void __launch_bounds__(256) vtrans() {
    __shared__ __nv_bfloat16 th[32][33], tl[32][33];
    const int bh = blockIdx.z, j0 = blockIdx.x * 32, d0 = blockIdx.y * 32;
    const int tx = threadIdx.x & 31, ty = threadIdx.x >> 5;
    const size_t src = ((size_t)bh * 1024 + j0) * 64 + d0;
    for (int r = ty; r < 32; r += 8) {
        th[r][tx] = vb_hi[src + (size_t)r * 64 + tx];
        tl[r][tx] = vb_lo[src + (size_t)r * 64 + tx];
    }
    __syncthreads();
    const size_t dst = ((size_t)bh * 64 + d0) * 1024 + j0;
    for (int r = ty; r < 32; r += 8) {
        vbT_hi[dst + (size_t)r * 1024 + tx] = th[tx][r];
        vbT_lo[dst + (size_t)r * 1024 + tx] = tl[tx][r];
    }
}

// ---------------------------------------------------------------------------
// sim = Q @ K^T per bh.  CTA 128x128, K=64 single chunk, 2 CTA/SM
// ---------------------------------------------------------------------------
#define SIM_SMEM (4 * 128 * S64 * 2)       // 73728 B

__global__ void __launch_bounds__(256, 2) sim_mma() {
    extern __shared__ __nv_bfloat16 smp[];
    const int tid = threadIdx.x, wid = tid >> 5, lane = tid & 31;
    const int q = lane & 3, g = lane >> 2;
    const int j0 = blockIdx.x * 128, i0 = blockIdx.y * 128, bh = blockIdx.z;
    const int wm0 = (wid >> 2) * 64, wn0 = (wid & 3) * 32;

    tile_async64<S64>(smp + 0 * 128 * S64, qb_hi + ((size_t)(bh << 10) + i0) * 64, 128, 64, tid);
    tile_async64<S64>(smp + 1 * 128 * S64, qb_lo + ((size_t)(bh << 10) + i0) * 64, 128, 64, tid);
    tile_async64<S64>(smp + 2 * 128 * S64, kb_hi + ((size_t)(bh << 10) + j0) * 64, 128, 64, tid);
    tile_async64<S64>(smp + 3 * 128 * S64, kb_lo + ((size_t)(bh << 10) + j0) * 64, 128, 64, tid);
    CP_COMMIT();
    CP_WAIT0();
    __syncthreads();

    float c[4][4][4] = {};
    gemm_tile44<S64, 64>(c, smp, wm0, wn0, lane);

#pragma unroll
    for (int mf = 0; mf < 4; mf++)
#pragma unroll
        for (int nf = 0; nf < 4; nf++) {
            int j = j0 + wn0 + nf * 8 + q * 2;
#pragma unroll
            for (int half = 0; half < 2; half++) {
                int i = i0 + wm0 + mf * 16 + g + half * 8;
                *(float2*)(g_sim + ((size_t)(bh << 10) + i) * 1024 + j) =
                    make_float2(c[mf][nf][half * 2], c[mf][nf][half * 2 + 1]);
            }
        }
}

// ---------------------------------------------------------------------------
// entmax-1.5: warp per row, 32 elems/thread in regs, Newton
// ---------------------------------------------------------------------------
__device__ __forceinline__ float warp_max(float v) {
#pragma unroll
    for (int o = 16; o; o >>= 1) v = fmaxf(v, __shfl_xor_sync(0xffffffffu, v, o));
    return v;
}
__device__ __forceinline__ float warp_sum(float v) {
#pragma unroll
    for (int o = 16; o; o >>= 1) v += __shfl_xor_sync(0xffffffffu, v, o);
    return v;
}

__global__ void __launch_bounds__(256) entmax_k() {
    const int lane = threadIdx.x & 31, wid = threadIdx.x >> 5;
    const size_t row = (size_t)blockIdx.x * 8 + wid;
    const float* p = g_sim + row * 1024;

    float z[32];
    float m = -1e30f;
#pragma unroll
    for (int j = 0; j < 8; j++) {
        float4 v = ((const float4*)p)[j * 32 + lane];
        z[j * 4 + 0] = v.x * 0.5f; z[j * 4 + 1] = v.y * 0.5f;
        z[j * 4 + 2] = v.z * 0.5f; z[j * 4 + 3] = v.w * 0.5f;
        m = fmaxf(m, fmaxf(fmaxf(z[j * 4], z[j * 4 + 1]),
                           fmaxf(z[j * 4 + 2], z[j * 4 + 3])));
    }
    m = warp_max(m);
#pragma unroll
    for (int i = 0; i < 32; i++) z[i] -= m;

    float tau = -1.0f;
#pragma unroll 1
    for (int it = 0; it < 12; it++) {
        float s1 = 0.f, s2 = 0.f;
#pragma unroll
        for (int i = 0; i < 32; i++) {
            float r = z[i] - tau;
            if (r > 0.f) { s1 += r; s2 = fmaf(r, r, s2); }
        }
        s1 = warp_sum(s1);
        s2 = warp_sum(s2);
        tau += (s2 - 1.0f) / fmaxf(2.0f * s1, 1e-20f);
    }
#pragma unroll
    for (int j = 0; j < 8; j++) {
        float a0 = fmaxf(z[j * 4 + 0] - tau, 0.f), a1 = fmaxf(z[j * 4 + 1] - tau, 0.f);
        float a2 = fmaxf(z[j * 4 + 2] - tau, 0.f), a3 = fmaxf(z[j * 4 + 3] - tau, 0.f);
        a0 *= a0; a1 *= a1; a2 *= a2; a3 *= a3;
        __nv_bfloat16 l0, l1, l2, l3;
        uint32_t h01 = packsplit(a0, a1, l0, l1);
        uint32_t h23 = packsplit(a2, a3, l2, l3);
        size_t base = row * 1024 + (size_t)(j * 32 + lane) * 4;
        *(uint2*)(ab_hi + base) = make_uint2(h01, h23);
        *(uint2*)(ab_lo + base) = make_uint2(pack2(l0, l1), pack2(l2, l3));
    }
}

// ---------------------------------------------------------------------------
// out = attn @ V per bh.  CTA 128x64, 3-stage pipeline, 32 chunks
// ---------------------------------------------------------------------------
__global__ void __launch_bounds__(256, 2) av_mma() {
    extern __shared__ __nv_bfloat16 smp[];
    const int tid = threadIdx.x, wid = tid >> 5, lane = tid & 31;
    const int q = lane & 3, g = lane >> 2;
    const int i0 = blockIdx.x * 128, bh = blockIdx.y;
    const int wm0 = (wid & 3) * 32, wn0 = (wid >> 2) * 32;

    float c[2][4][4] = {};
    pipe_gemm<32>(c, smp,
                  ab_hi + ((size_t)(bh << 10) + i0) * 1024,
                  ab_lo + ((size_t)(bh << 10) + i0) * 1024,
                  vbT_hi + (size_t)bh * 64 * 1024,
                  vbT_lo + (size_t)bh * 64 * 1024,
                  1024, tid, wm0, wn0, lane);

    const int b = bh >> 3, h = bh & 7;
#pragma unroll
    for (int mf = 0; mf < 2; mf++)
#pragma unroll
        for (int nf = 0; nf < 4; nf++) {
            int d = wn0 + nf * 8 + q * 2;
#pragma unroll
            for (int half = 0; half < 2; half++) {
                int i = i0 + wm0 + mf * 16 + g + half * 8;
                __nv_bfloat16 l0, l1;
                uint32_t hp = packsplit(c[mf][nf][half * 2],
                                        c[mf][nf][half * 2 + 1], l0, l1);
                size_t base = ((size_t)b * 1024 + i) * 512 + h * 64 + d;
                *(uint32_t*)(ob_hi + base) = hp;
                *(uint32_t*)(ob_lo + base) = pack2(l0, l1);
            }
        }
}

// ---------------------------------------------------------------------------
// final = o @ w_out  (M=4096, N=512, K=512): tile 128x64, 3-stage
// ---------------------------------------------------------------------------
__global__ void __launch_bounds__(256, 2) out_mma(float* __restrict__ out) {
    extern __shared__ __nv_bfloat16 smp[];
    const int tid = threadIdx.x, wid = tid >> 5, lane = tid & 31;
    const int q = lane & 3, g = lane >> 2;
    const int row0 = blockIdx.y * 128, col0 = blockIdx.x * 64;
    const int wm0 = (wid & 3) * 32, wn0 = (wid >> 2) * 32;

    float c[2][4][4] = {};
    pipe_gemm<16>(c, smp,
                  ob_hi + (size_t)row0 * 512, ob_lo + (size_t)row0 * 512,
                  woutT_hi + (size_t)col0 * 512, woutT_lo + (size_t)col0 * 512,
                  512, tid, wm0, wn0, lane);

#pragma unroll
    for (int mf = 0; mf < 2; mf++)
#pragma unroll
        for (int nf = 0; nf < 4; nf++) {
            int n = col0 + wn0 + nf * 8 + q * 2;
#pragma unroll
            for (int half = 0; half < 2; half++) {
                int m = row0 + wm0 + mf * 16 + g + half * 8;
                *(float2*)(out + (size_t)m * 512 + n) =
                    make_float2(c[mf][nf][half * 2], c[mf][nf][half * 2 + 1]);
            }
        }
}

// ---------------------------------------------------------------------------
// kernel_launch
// ---------------------------------------------------------------------------
extern "C" void kernel_launch(void* const* d_in, const int* in_sizes, int n_in,
                              void* d_out, int out_size) {
    (void)in_sizes; (void)n_in; (void)out_size;
    const float* x     = (const float*)d_in[0];
    const float* w_qkv = (const float*)d_in[1];
    const float* w_out = (const float*)d_in[2];
    float* out = (float*)d_out;

    cudaFuncSetAttribute(qkv_mma, cudaFuncAttributeMaxDynamicSharedMemorySize, PIPE_SMEM);
    cudaFuncSetAttribute(sim_mma, cudaFuncAttributeMaxDynamicSharedMemorySize, SIM_SMEM);
    cudaFuncSetAttribute(av_mma,  cudaFuncAttributeMaxDynamicSharedMemorySize, PIPE_SMEM);
    cudaFuncSetAttribute(out_mma, cudaFuncAttributeMaxDynamicSharedMemorySize, PIPE_SMEM);

    __nv_bfloat16 *wqh, *wql, *woh, *wol;
    cudaGetSymbolAddress((void**)&wqh, wqkvT_hi);
    cudaGetSymbolAddress((void**)&wql, wqkvT_lo);
    cudaGetSymbolAddress((void**)&woh, woutT_hi);
    cudaGetSymbolAddress((void**)&wol, woutT_lo);

    conv_x<<<2048, 256>>>(x);
    conv_w<<<3072, 256>>>(w_qkv, wqh, wql, 1536);
    conv_w<<<1024, 256>>>(w_out, woh, wol, 512);
    qkv_mma<<<dim3(24, 32), 256, PIPE_SMEM>>>();
    vtrans<<<dim3(32, 2, 32), 256>>>();
    sim_mma<<<dim3(8, 8, 32), 256, SIM_SMEM>>>();
    entmax_k<<<4096, 256>>>();
    av_mma<<<dim3(8, 32), 256, PIPE_SMEM>>>();
    out_mma<<<dim3(8, 32), 256, PIPE_SMEM>>>(out);
}